// round 7
// baseline (speedup 1.0000x reference)
#include <cuda_runtime.h>
#include <cuda_bf16.h>
#include <math.h>
#include <stdint.h>

// ---------------- problem constants ----------------
#define MROWS   400000
#define NBAG    8
#define NPER    50000
#define DIN     256
#define HDIM    128
#define INV_TAU (1.0f/0.3f)
#define LN_EPS  1e-5f
#define CHUNK   512
#define NCHUNK2 98               // ceil(50000/512)

// ---------------- scratch globals ----------------
__device__ __nv_bfloat16 g_h2b[(size_t)MROWS * HDIM];   // 102.4 MB (bf16)
__device__ float g_scores[MROWS];
__device__ float g_bagmax[NBAG];
__device__ float g_pvec[NBAG * NCHUNK2 * HDIM];
__device__ float g_pZ[NBAG * NCHUNK2];
// bf16 hi/lo weights, dense [n][k]: [W1half0, W1half1, W2, Wa1] x [hi 32KB | lo 32KB]
__device__ __align__(16) unsigned char g_wsw[4 * 65536];

// ---------------- smem layout (bytes) ----------------
#define A_HI_OFF  0
#define A_LO_OFF  34816
#define B0_OFF    69632          // hi at +0, lo at +34816
#define B1_OFF    139264
#define BIAS_OFF  208896         // 1025 floats
#define RED_OFF   213000         // 256 floats cross-warp reduce buffer (8B aligned)
#define SMEM_SZ   214032
#define BLO       34816          // hi->lo offset within a B buffer

__device__ __forceinline__ uint32_t smem_to_u32(const void* p) {
    uint32_t a;
    asm("{ .reg .u64 t; cvta.to.shared.u64 t, %1; cvt.u32.u64 %0, t; }" : "=r"(a) : "l"(p));
    return a;
}

#define LDM4(r, addr) \
    asm volatile("ldmatrix.sync.aligned.m8n8.x4.shared.b16 {%0,%1,%2,%3}, [%4];" \
        : "=r"((r)[0]), "=r"((r)[1]), "=r"((r)[2]), "=r"((r)[3]) : "r"(addr))

#define MMA16816(c, a, b0, b1) \
    asm volatile("mma.sync.aligned.m16n8k16.row.col.f32.bf16.bf16.f32 " \
        "{%0,%1,%2,%3}, {%4,%5,%6,%7}, {%8,%9}, {%0,%1,%2,%3};" \
        : "+f"((c)[0]), "+f"((c)[1]), "+f"((c)[2]), "+f"((c)[3]) \
        : "r"((a)[0]), "r"((a)[1]), "r"((a)[2]), "r"((a)[3]), "r"(b0), "r"(b1))

#define CP_ASYNC16(saddr, gptr) \
    asm volatile("cp.async.cg.shared.global [%0], [%1], 16;" :: "r"(saddr), "l"(gptr) : "memory")
#define CP_COMMIT() asm volatile("cp.async.commit_group;" ::: "memory")
#define CP_WAIT(n)  asm volatile("cp.async.wait_group %0;" :: "n"(n) : "memory")

// exact identity tanh: 1 - 2/(e^{2x}+1); abs err ~1e-7
__device__ __forceinline__ float fast_tanh(float x) {
    float e = __expf(2.0f * x);
    return 1.0f - __fdividef(2.0f, e + 1.0f);
}

// ---------------- weight prep: fp32 -> dense bf16 hi/lo [n][k] ----------------
__global__ void k_prep(const float* __restrict__ W1, const float* __restrict__ W2,
                       const float* __restrict__ Wa1)
{
    int mat = blockIdx.x;
    const float* W; int koff;
    if (mat == 0)      { W = W1;  koff = 0;   }
    else if (mat == 1) { W = W1;  koff = 128; }
    else if (mat == 2) { W = W2;  koff = 0;   }
    else               { W = Wa1; koff = 0;   }
    __nv_bfloat16* dh = (__nv_bfloat16*)(g_wsw + (size_t)mat * 65536);
    __nv_bfloat16* dl = dh + 16384;
    for (int idx = threadIdx.x; idx < 16384; idx += blockDim.x) {
        int n = idx >> 7, k = idx & 127;
        float w = W[(size_t)(koff + k) * 128 + n];   // B[n][k] = W[k][n]
        __nv_bfloat16 h = __float2bfloat16(w);
        __nv_bfloat16 l = __float2bfloat16(w - __bfloat162float(h));
        dh[n * 128 + k] = h;
        dl[n * 128 + k] = l;
    }
}

// ---------------- staging ----------------
__device__ __forceinline__ void stage_w_async(uint32_t smb, int mat, uint32_t dstoff, int tid) {
    const unsigned char* src = g_wsw + (size_t)mat * 65536;
    unsigned long long gbase = (unsigned long long)__cvta_generic_to_global((void*)src);
#pragma unroll
    for (int i = 0; i < 8; i++) {
        int idx = tid + i * 256;
        int r = idx >> 4, q = idx & 15;
        uint32_t soff = (uint32_t)(r * 136 + q * 8) * 2u;
        unsigned long long goff = (unsigned long long)(r * 128 + q * 8) * 2ull;
        CP_ASYNC16(smb + dstoff + soff,        gbase + goff);
        CP_ASYNC16(smb + dstoff + BLO + soff,  gbase + 32768ull + goff);
    }
}

__device__ __forceinline__ uint32_t pack_hi(float a, float b, float& la, float& lb) {
    __nv_bfloat16 ha = __float2bfloat16(a), hb = __float2bfloat16(b);
    la = a - __bfloat162float(ha);
    lb = b - __bfloat162float(hb);
    return (uint32_t)__bfloat16_as_ushort(ha) | ((uint32_t)__bfloat16_as_ushort(hb) << 16);
}
__device__ __forceinline__ uint32_t pack_bf(float a, float b) {
    return (uint32_t)__bfloat16_as_ushort(__float2bfloat16(a)) |
           ((uint32_t)__bfloat16_as_ushort(__float2bfloat16(b)) << 16);
}

__device__ __forceinline__ void stage_x(char* sm, const float* __restrict__ x,
                                        size_t rowTile, int hh, int tid) {
#pragma unroll
    for (int i = 0; i < 16; i++) {
        int idx = tid + i * 256;
        int r = idx >> 5, c4 = idx & 31;
        float4 vv = *(const float4*)(x + (rowTile + r) * DIN + hh * 128 + c4 * 4);
        float l0, l1, l2, l3;
        uint32_t h0 = pack_hi(vv.x, vv.y, l0, l1);
        uint32_t h1 = pack_hi(vv.z, vv.w, l2, l3);
        uint32_t q0 = pack_bf(l0, l1), q1 = pack_bf(l2, l3);
        uint32_t off = (uint32_t)(r * 136 + c4 * 4) * 2;
        *(uint2*)(sm + A_HI_OFF + off) = make_uint2(h0, h1);
        *(uint2*)(sm + A_LO_OFF + off) = make_uint2(q0, q1);
    }
}

// ---------------- core MMA, 4(M)x2(N) warp grid ----------------
// warp wm (0..3) owns rows [wm*32, wm*32+32); wn (0..1) owns cols [wn*64, wn*64+64)
// acc[mt][nt][4]: mt = 16-row tile (0..1), nt = 8-col tile (0..7)
__device__ __forceinline__ void mma_block(uint32_t smb, uint32_t boff, int wm, int wn, int L,
                                          float (*acc)[8][4]) {
    const uint32_t aRow0 = (uint32_t)(wm * 32 + (L & 15)) * 136u;
    const uint32_t aK0   = 8u * (uint32_t)(L >> 4);
    const int g = L >> 3, rr = L & 7;
    const uint32_t bRow0 = (uint32_t)(wn * 64 + (g >> 1) * 8 + rr) * 136u;
    const uint32_t bK0   = 8u * (uint32_t)(g & 1);
#pragma unroll 2
    for (int ks = 0; ks < 8; ks++) {
        uint32_t ah[2][4], al[2][4];
#pragma unroll
        for (int mt = 0; mt < 2; mt++) {
            uint32_t aaddr = smb + A_HI_OFF +
                (aRow0 + (uint32_t)mt * (16u * 136u) + aK0 + (uint32_t)ks * 16u) * 2u;
            LDM4(ah[mt], aaddr);
            LDM4(al[mt], aaddr + (A_LO_OFF - A_HI_OFF));
        }
#pragma unroll
        for (int nt2 = 0; nt2 < 4; nt2++) {
            uint32_t bh[4], bl[4];
            uint32_t baddr = smb + boff +
                (bRow0 + (uint32_t)nt2 * (16u * 136u) + bK0 + (uint32_t)ks * 16u) * 2u;
            LDM4(bh, baddr);
            LDM4(bl, baddr + BLO);
#pragma unroll
            for (int mt = 0; mt < 2; mt++) {
                MMA16816(acc[mt][2 * nt2],     ah[mt], bh[0], bh[1]);
                MMA16816(acc[mt][2 * nt2 + 1], ah[mt], bh[2], bh[3]);
                MMA16816(acc[mt][2 * nt2],     ah[mt], bl[0], bl[1]);
                MMA16816(acc[mt][2 * nt2 + 1], ah[mt], bl[2], bl[3]);
                MMA16816(acc[mt][2 * nt2],     al[mt], bh[0], bh[1]);
                MMA16816(acc[mt][2 * nt2 + 1], al[mt], bh[2], bh[3]);
            }
        }
    }
}

// ---------------- LN + ReLU epilogue (cross-warp via smem partials) ----------------
// red: 256-float buffer; row r partials at red[r*2 + wn]
__device__ __forceinline__ void ln_relu(float (*acc)[8][4], const float* bias, int boff,
                                        int wm, int wn, int L, float* red) {
    const int q2 = 2 * (L & 3);
    const int c0 = wn * 64 + q2;
    const int rb0 = wm * 32 + (L >> 2);   // tile-relative rows rb0, rb0+8 (mt=0), +16, +24 (mt=1)

    // bias add + per-row partial sums over this warp's 64 cols
    float ps[2][2];
#pragma unroll
    for (int mt = 0; mt < 2; mt++) {
        float s0 = 0.f, s1 = 0.f;
#pragma unroll
        for (int nt = 0; nt < 8; nt++) {
            int c = c0 + nt * 8;
            float b0 = bias[boff + c], b1v = bias[boff + c + 1];
            acc[mt][nt][0] += b0; acc[mt][nt][1] += b1v;
            acc[mt][nt][2] += b0; acc[mt][nt][3] += b1v;
            s0 += acc[mt][nt][0] + acc[mt][nt][1];
            s1 += acc[mt][nt][2] + acc[mt][nt][3];
        }
        s0 += __shfl_xor_sync(0xffffffffu, s0, 1); s0 += __shfl_xor_sync(0xffffffffu, s0, 2);
        s1 += __shfl_xor_sync(0xffffffffu, s1, 1); s1 += __shfl_xor_sync(0xffffffffu, s1, 2);
        ps[mt][0] = s0; ps[mt][1] = s1;
    }
    if ((L & 3) == 0) {
#pragma unroll
        for (int mt = 0; mt < 2; mt++) {
            red[(rb0 + mt * 16) * 2 + wn]     = ps[mt][0];
            red[(rb0 + mt * 16 + 8) * 2 + wn] = ps[mt][1];
        }
    }
    __syncthreads();
    float mu[2][2];
#pragma unroll
    for (int mt = 0; mt < 2; mt++) {
        mu[mt][0] = (red[(rb0 + mt * 16) * 2] + red[(rb0 + mt * 16) * 2 + 1]) * 0.0078125f;
        mu[mt][1] = (red[(rb0 + mt * 16 + 8) * 2] + red[(rb0 + mt * 16 + 8) * 2 + 1]) * 0.0078125f;
    }
    __syncthreads();  // done reading mean partials; reuse red for var
#pragma unroll
    for (int mt = 0; mt < 2; mt++) {
        float v0 = 0.f, v1 = 0.f;
#pragma unroll
        for (int nt = 0; nt < 8; nt++) {
            float d;
            d = acc[mt][nt][0] - mu[mt][0]; v0 = fmaf(d, d, v0);
            d = acc[mt][nt][1] - mu[mt][0]; v0 = fmaf(d, d, v0);
            d = acc[mt][nt][2] - mu[mt][1]; v1 = fmaf(d, d, v1);
            d = acc[mt][nt][3] - mu[mt][1]; v1 = fmaf(d, d, v1);
        }
        v0 += __shfl_xor_sync(0xffffffffu, v0, 1); v0 += __shfl_xor_sync(0xffffffffu, v0, 2);
        v1 += __shfl_xor_sync(0xffffffffu, v1, 1); v1 += __shfl_xor_sync(0xffffffffu, v1, 2);
        ps[mt][0] = v0; ps[mt][1] = v1;
    }
    if ((L & 3) == 0) {
#pragma unroll
        for (int mt = 0; mt < 2; mt++) {
            red[(rb0 + mt * 16) * 2 + wn]     = ps[mt][0];
            red[(rb0 + mt * 16 + 8) * 2 + wn] = ps[mt][1];
        }
    }
    __syncthreads();
#pragma unroll
    for (int mt = 0; mt < 2; mt++) {
        float i0 = rsqrtf(fmaf(red[(rb0 + mt * 16) * 2] + red[(rb0 + mt * 16) * 2 + 1],
                               0.0078125f, LN_EPS));
        float i1 = rsqrtf(fmaf(red[(rb0 + mt * 16 + 8) * 2] + red[(rb0 + mt * 16 + 8) * 2 + 1],
                               0.0078125f, LN_EPS));
#pragma unroll
        for (int nt = 0; nt < 8; nt++) {
            int c = c0 + nt * 8;
            float g0 = bias[boff + 128 + c], g1v = bias[boff + 128 + c + 1];
            float e0 = bias[boff + 256 + c], e1v = bias[boff + 256 + c + 1];
            acc[mt][nt][0] = fmaxf(fmaf((acc[mt][nt][0] - mu[mt][0]) * i0, g0, e0), 0.f);
            acc[mt][nt][1] = fmaxf(fmaf((acc[mt][nt][1] - mu[mt][0]) * i0, g1v, e1v), 0.f);
            acc[mt][nt][2] = fmaxf(fmaf((acc[mt][nt][2] - mu[mt][1]) * i1, g0, e0), 0.f);
            acc[mt][nt][3] = fmaxf(fmaf((acc[mt][nt][3] - mu[mt][1]) * i1, g1v, e1v), 0.f);
        }
    }
    __syncthreads();  // red free for next use
}

// write activated fragments into A hi/lo smem as next-phase A operand
__device__ __forceinline__ void store_A(char* sm, float (*acc)[8][4], int wm, int wn, int L) {
    const int q2 = 2 * (L & 3);
    const int c0 = wn * 64 + q2;
#pragma unroll
    for (int mt = 0; mt < 2; mt++) {
        const int r0 = wm * 32 + mt * 16 + (L >> 2), r1 = r0 + 8;
#pragma unroll
        for (int nt = 0; nt < 8; nt++) {
            int c = c0 + nt * 8;
            float l0, l1;
            uint32_t h = pack_hi(acc[mt][nt][0], acc[mt][nt][1], l0, l1);
            uint32_t l = pack_bf(l0, l1);
            *(uint32_t*)(sm + A_HI_OFF + (r0 * 136 + c) * 2) = h;
            *(uint32_t*)(sm + A_LO_OFF + (r0 * 136 + c) * 2) = l;
            h = pack_hi(acc[mt][nt][2], acc[mt][nt][3], l0, l1);
            l = pack_bf(l0, l1);
            *(uint32_t*)(sm + A_HI_OFF + (r1 * 136 + c) * 2) = h;
            *(uint32_t*)(sm + A_LO_OFF + (r1 * 136 + c) * 2) = l;
        }
    }
}

// ---------------- fused row kernel ----------------
__global__ void __launch_bounds__(256)
k_rows_mma(const float* __restrict__ x,
           const float* __restrict__ b1, const float* __restrict__ g1, const float* __restrict__ be1,
           const float* __restrict__ b2, const float* __restrict__ g2, const float* __restrict__ be2,
           const float* __restrict__ ba1, const float* __restrict__ ba2, const float* __restrict__ Wa2)
{
    extern __shared__ char sm[];
    const uint32_t smb = smem_to_u32(sm);
    const int tid = threadIdx.x;
    const int w = tid >> 5, L = tid & 31;
    const int wm = w >> 1, wn = w & 1;
    const size_t rowTile = (size_t)blockIdx.x * 128;
    float* bias = (float*)(sm + BIAS_OFF);
    float* red  = (float*)(sm + RED_OFF);

    stage_w_async(smb, 0, B0_OFF, tid); CP_COMMIT();   // G0: W1 half0
    stage_w_async(smb, 1, B1_OFF, tid); CP_COMMIT();   // G1: W1 half1

    if (tid < 128) {
        bias[tid]       = b1[tid];  bias[128 + tid] = g1[tid];  bias[256 + tid] = be1[tid];
        bias[384 + tid] = b2[tid];  bias[512 + tid] = g2[tid];  bias[640 + tid] = be2[tid];
        bias[768 + tid] = ba1[tid]; bias[896 + tid] = Wa2[tid];
    }
    if (tid == 0) bias[1024] = ba2[0];

    float acc[2][8][4];
#pragma unroll
    for (int mt = 0; mt < 2; mt++)
#pragma unroll
        for (int nt = 0; nt < 8; nt++)
#pragma unroll
            for (int j = 0; j < 4; j++) acc[mt][nt][j] = 0.f;

    // ===== PHASE 1: x @ W1 (K=256, two K=128 blocks) =====
    stage_x(sm, x, rowTile, 0, tid);
    CP_WAIT(1);
    __syncthreads();
    mma_block(smb, B0_OFF, wm, wn, L, acc);
    __syncthreads();
    stage_w_async(smb, 2, B0_OFF, tid); CP_COMMIT();   // G2: W2
    stage_x(sm, x, rowTile, 1, tid);
    CP_WAIT(1);
    __syncthreads();
    mma_block(smb, B1_OFF, wm, wn, L, acc);
    __syncthreads();
    stage_w_async(smb, 3, B1_OFF, tid); CP_COMMIT();   // G3: Wa1

    ln_relu(acc, bias, 0, wm, wn, L, red);
    store_A(sm, acc, wm, wn, L);
    CP_WAIT(1);
    __syncthreads();

    // ===== PHASE 2: h1 @ W2 =====
#pragma unroll
    for (int mt = 0; mt < 2; mt++)
#pragma unroll
        for (int nt = 0; nt < 8; nt++)
#pragma unroll
            for (int j = 0; j < 4; j++) acc[mt][nt][j] = 0.f;
    mma_block(smb, B0_OFF, wm, wn, L, acc);
    __syncthreads();
    ln_relu(acc, bias, 384, wm, wn, L, red);

    // stage h2 bf16 through B0 region, coalesced store; refresh A
    {
        uint32_t* Hs = (uint32_t*)(sm + B0_OFF);     // [128][68] uints (bf16x2)
        const int cu0 = wn * 32 + (L & 3);
#pragma unroll
        for (int mt = 0; mt < 2; mt++) {
            const int r0 = wm * 32 + mt * 16 + (L >> 2), r1 = r0 + 8;
#pragma unroll
            for (int nt = 0; nt < 8; nt++) {
                int cu = cu0 + nt * 4;
                Hs[r0 * 68 + cu] = pack_bf(acc[mt][nt][0], acc[mt][nt][1]);
                Hs[r1 * 68 + cu] = pack_bf(acc[mt][nt][2], acc[mt][nt][3]);
            }
        }
        store_A(sm, acc, wm, wn, L);
        CP_WAIT(0);               // G3 (Wa1) complete
        __syncthreads();
#pragma unroll
        for (int i = 0; i < 8; i++) {
            int idx = tid + i * 256;
            int r = idx >> 4, q = idx & 15;
            uint4 vv = *(uint4*)(Hs + r * 68 + q * 4);
            *(uint4*)((char*)(g_h2b + (rowTile + r) * HDIM) + q * 16) = vv;
        }
    }

    // ===== PHASE 3: h2 @ Wa1 -> tanh -> dot Wa2 -> scores =====
#pragma unroll
    for (int mt = 0; mt < 2; mt++)
#pragma unroll
        for (int nt = 0; nt < 8; nt++)
#pragma unroll
            for (int j = 0; j < 4; j++) acc[mt][nt][j] = 0.f;
    mma_block(smb, B1_OFF, wm, wn, L, acc);

    {
        const int q2 = 2 * (L & 3);
        const int c0 = wn * 64 + q2;
        const int rb0 = wm * 32 + (L >> 2);
        float ps[2][2];
#pragma unroll
        for (int mt = 0; mt < 2; mt++) {
            float p0 = 0.f, p1 = 0.f;
#pragma unroll
            for (int nt = 0; nt < 8; nt++) {
                int c = c0 + nt * 8;
                float wa0 = bias[896 + c], wa1v = bias[896 + c + 1];
                float bb0 = bias[768 + c], bb1 = bias[768 + c + 1];
                p0 = fmaf(fast_tanh(acc[mt][nt][0] + bb0), wa0, p0);
                p0 = fmaf(fast_tanh(acc[mt][nt][1] + bb1), wa1v, p0);
                p1 = fmaf(fast_tanh(acc[mt][nt][2] + bb0), wa0, p1);
                p1 = fmaf(fast_tanh(acc[mt][nt][3] + bb1), wa1v, p1);
            }
            p0 += __shfl_xor_sync(0xffffffffu, p0, 1); p0 += __shfl_xor_sync(0xffffffffu, p0, 2);
            p1 += __shfl_xor_sync(0xffffffffu, p1, 1); p1 += __shfl_xor_sync(0xffffffffu, p1, 2);
            ps[mt][0] = p0; ps[mt][1] = p1;
        }
        __syncthreads();  // Hs reads done before red overwrite? (red separate) — protects nothing else; cheap
        if ((L & 3) == 0) {
#pragma unroll
            for (int mt = 0; mt < 2; mt++) {
                red[(rb0 + mt * 16) * 2 + wn]     = ps[mt][0];
                red[(rb0 + mt * 16 + 8) * 2 + wn] = ps[mt][1];
            }
        }
        __syncthreads();
        if (tid < 128) {
            g_scores[rowTile + tid] = red[tid * 2] + red[tid * 2 + 1] + bias[1024];
        }
    }
}

// ---------------- per-bag score max ----------------
__global__ __launch_bounds__(256)
void k_max()
{
    const int bag = blockIdx.x;
    const int tid = threadIdx.x;
    __shared__ float red[256];
    float m = -3.4e38f;
    const float* sp = g_scores + (size_t)bag * NPER;
    for (int i = tid; i < NPER; i += 256) m = fmaxf(m, sp[i]);
    red[tid] = m;
    __syncthreads();
    for (int off = 128; off; off >>= 1) {
        if (tid < off) red[tid] = fmaxf(red[tid], red[tid + off]);
        __syncthreads();
    }
    if (tid == 0) g_bagmax[bag] = red[0];
}

// ---------------- weighted partial sums (chunks of 512 rows, bf16 h2) ----------------
__global__ __launch_bounds__(256)
void k_wsum()
{
    const int b = blockIdx.x / NCHUNK2;
    const int c = blockIdx.x % NCHUNK2;
    const int tid = threadIdx.x;
    const int base = c * CHUNK;
    const int cnt = min(CHUNK, NPER - base);
    __shared__ float wrow[CHUNK];
    __shared__ float2 sred[256];

    const float bm = g_bagmax[b];
    {
        int i0 = tid, i1 = tid + 256;
        wrow[i0] = (i0 < cnt) ? expf((g_scores[(size_t)b * NPER + base + i0] - bm) * INV_TAU) : 0.f;
        wrow[i1] = (i1 < cnt) ? expf((g_scores[(size_t)b * NPER + base + i1] - bm) * INV_TAU) : 0.f;
    }
    __syncthreads();

    const int c2 = tid & 63;
    const int rg = tid >> 6;
    const uint32_t* hp = (const uint32_t*)(g_h2b + ((size_t)b * NPER + base) * HDIM) + c2;

    float2 a0 = {0.f,0.f}, a1 = {0.f,0.f}, a2 = {0.f,0.f}, a3 = {0.f,0.f};
    int n = rg;
    for (; n + 12 < cnt; n += 16) {
        uint32_t u0 = hp[(size_t)n * 64];
        uint32_t u1 = hp[(size_t)(n + 4) * 64];
        uint32_t u2 = hp[(size_t)(n + 8) * 64];
        uint32_t u3 = hp[(size_t)(n + 12) * 64];
        float2 f0 = __bfloat1622float2(*(const __nv_bfloat162*)&u0);
        float2 f1 = __bfloat1622float2(*(const __nv_bfloat162*)&u1);
        float2 f2 = __bfloat1622float2(*(const __nv_bfloat162*)&u2);
        float2 f3 = __bfloat1622float2(*(const __nv_bfloat162*)&u3);
        float w0 = wrow[n], w1 = wrow[n + 4], w2 = wrow[n + 8], w3 = wrow[n + 12];
        a0.x = fmaf(w0, f0.x, a0.x); a0.y = fmaf(w0, f0.y, a0.y);
        a1.x = fmaf(w1, f1.x, a1.x); a1.y = fmaf(w1, f1.y, a1.y);
        a2.x = fmaf(w2, f2.x, a2.x); a2.y = fmaf(w2, f2.y, a2.y);
        a3.x = fmaf(w3, f3.x, a3.x); a3.y = fmaf(w3, f3.y, a3.y);
    }
    for (; n < cnt; n += 4) {
        uint32_t u = hp[(size_t)n * 64];
        float2 f = __bfloat1622float2(*(const __nv_bfloat162*)&u);
        float wv = wrow[n];
        a0.x = fmaf(wv, f.x, a0.x); a0.y = fmaf(wv, f.y, a0.y);
    }
    float2 at;
    at.x = (a0.x + a1.x) + (a2.x + a3.x);
    at.y = (a0.y + a1.y) + (a2.y + a3.y);
    sred[tid] = at;
    __syncthreads();
    if (tid < 64) {
        float2 t0 = sred[tid], t1 = sred[tid + 64], t2 = sred[tid + 128], t3 = sred[tid + 192];
        float* pv = g_pvec + ((size_t)b * NCHUNK2 + c) * HDIM;
        pv[2 * tid]     = (t0.x + t1.x) + (t2.x + t3.x);
        pv[2 * tid + 1] = (t0.y + t1.y) + (t2.y + t3.y);
    }

    __syncthreads();
    float z = wrow[tid] + wrow[tid + 256];
    wrow[tid] = z;
    __syncthreads();
    for (int off = 128; off; off >>= 1) {
        if (tid < off) wrow[tid] += wrow[tid + off];
        __syncthreads();
    }
    if (tid == 0) g_pZ[b * NCHUNK2 + c] = wrow[0];
}

// ---------------- final heads ----------------
__global__ __launch_bounds__(128)
void k_final(const float* __restrict__ Wc1, const float* __restrict__ bc1,
             const float* __restrict__ Wc2, const float* __restrict__ bc2,
             const float* __restrict__ Ws1, const float* __restrict__ bs1,
             const float* __restrict__ Ws2, const float* __restrict__ bs2,
             float* __restrict__ out)
{
    const int bag = blockIdx.x;
    const int tid = threadIdx.x;
    __shared__ float bagn[128];
    __shared__ float hid[128];
    __shared__ float redz[128];
    __shared__ float hs[64];

    float vv = 0.0f;
    for (int c = 0; c < NCHUNK2; c++)
        vv += g_pvec[((size_t)bag * NCHUNK2 + c) * HDIM + tid];

    float zp = 0.0f;
    for (int c = tid; c < NCHUNK2; c += 128)
        zp += g_pZ[bag * NCHUNK2 + c];
    redz[tid] = zp;
    __syncthreads();
    for (int off = 64; off; off >>= 1) {
        if (tid < off) redz[tid] += redz[tid + off];
        __syncthreads();
    }
    const float Z = redz[0];
    bagn[tid] = vv / Z;
    __syncthreads();

    {
        float h = bc1[tid];
        for (int k = 0; k < 128; k++) h = fmaf(bagn[k], Wc1[k * 128 + tid], h);
        hid[tid] = fmaxf(h, 0.0f);
    }
    if (tid < 64) {
        float h = bs1[tid];
        for (int k = 0; k < 128; k++) h = fmaf(bagn[k], Ws1[k * 64 + tid], h);
        hs[tid] = fmaxf(h, 0.0f);
    }
    __syncthreads();

    if (tid < 2) {
        float s = bc2[tid];
        for (int j = 0; j < 128; j++) s = fmaf(hid[j], Wc2[j * 2 + tid], s);
        out[bag * 2 + tid] = s;
    }
    if (tid == 2) {
        float r = bs2[0];
        for (int j = 0; j < 64; j++) r = fmaf(hs[j], Ws2[j], r);
        out[16 + bag] = r;
    }
}

extern "C" void kernel_launch(void* const* d_in, const int* in_sizes, int n_in,
                              void* d_out, int out_size)
{
    const float* x   = (const float*)d_in[0];
    const float* W1  = (const float*)d_in[1];
    const float* b1  = (const float*)d_in[2];
    const float* g1  = (const float*)d_in[3];
    const float* be1 = (const float*)d_in[4];
    const float* W2  = (const float*)d_in[5];
    const float* b2  = (const float*)d_in[6];
    const float* g2  = (const float*)d_in[7];
    const float* be2 = (const float*)d_in[8];
    const float* Wa1 = (const float*)d_in[9];
    const float* ba1 = (const float*)d_in[10];
    const float* Wa2 = (const float*)d_in[11];
    const float* ba2 = (const float*)d_in[12];
    const float* Wc1 = (const float*)d_in[13];
    const float* bc1 = (const float*)d_in[14];
    const float* Wc2 = (const float*)d_in[15];
    const float* bc2 = (const float*)d_in[16];
    const float* Ws1 = (const float*)d_in[17];
    const float* bs1 = (const float*)d_in[18];
    const float* Ws2 = (const float*)d_in[19];
    const float* bs2 = (const float*)d_in[20];
    float* out = (float*)d_out;

    cudaFuncSetAttribute(k_rows_mma, cudaFuncAttributeMaxDynamicSharedMemorySize, SMEM_SZ);

    k_prep<<<4, 256>>>(W1, W2, Wa1);
    k_rows_mma<<<MROWS / 128, 256, SMEM_SZ>>>(x, b1, g1, be1, b2, g2, be2, ba1, ba2, Wa2);
    k_max<<<NBAG, 256>>>();
    k_wsum<<<NBAG * NCHUNK2, 256>>>();
    k_final<<<NBAG, 128>>>(Wc1, bc1, Wc2, bc2, Ws1, bs1, Ws2, bs2, out);
}

// round 8
// speedup vs baseline: 1.1849x; 1.1849x over previous
#include <cuda_runtime.h>
#include <cuda_bf16.h>
#include <math.h>
#include <stdint.h>

// ---------------- problem constants ----------------
#define MROWS   400000
#define NBAG    8
#define NPER    50000
#define DIN     256
#define HDIM    128
#define INV_TAU (1.0f/0.3f)
#define LN_EPS  1e-5f
#define CHUNK   512
#define NCHUNK2 98               // ceil(50000/512)

// ---------------- scratch globals ----------------
__device__ __nv_bfloat16 g_h2b[(size_t)MROWS * HDIM];   // 102.4 MB (bf16)
__device__ float g_scores[MROWS];
__device__ float g_bagmax[NBAG];
__device__ float g_pvec[NBAG * NCHUNK2 * HDIM];
__device__ float g_pZ[NBAG * NCHUNK2];
// bf16 hi/lo weights, dense [n][k]: [W1half0, W1half1, W2, Wa1] x [hi 32KB | lo 32KB]
__device__ __align__(16) unsigned char g_wsw[4 * 65536];

// ---------------- smem layout (bytes), single CTA = 106512 -> 2 CTAs/SM ----------------
#define B_HI_OFF  0              // weight buffer hi [128][136] bf16
#define BLO       34816          // hi -> lo offset
#define SCR_OFF   69632          // 32768: per-thread A-lo fragment scratch [ks][tid][16B]
#define BIAS_OFF  102400         // 1025 floats
#define SMEM_SZ   106512

__device__ __forceinline__ uint32_t smem_to_u32(const void* p) {
    uint32_t a;
    asm("{ .reg .u64 t; cvta.to.shared.u64 t, %1; cvt.u32.u64 %0, t; }" : "=r"(a) : "l"(p));
    return a;
}

#define LDM4(r, addr) \
    asm volatile("ldmatrix.sync.aligned.m8n8.x4.shared.b16 {%0,%1,%2,%3}, [%4];" \
        : "=r"((r)[0]), "=r"((r)[1]), "=r"((r)[2]), "=r"((r)[3]) : "r"(addr))

#define MMA16816(c, a, b0, b1) \
    asm volatile("mma.sync.aligned.m16n8k16.row.col.f32.bf16.bf16.f32 " \
        "{%0,%1,%2,%3}, {%4,%5,%6,%7}, {%8,%9}, {%0,%1,%2,%3};" \
        : "+f"((c)[0]), "+f"((c)[1]), "+f"((c)[2]), "+f"((c)[3]) \
        : "r"((a)[0]), "r"((a)[1]), "r"((a)[2]), "r"((a)[3]), "r"(b0), "r"(b1))

#define CP_ASYNC16(saddr, gptr) \
    asm volatile("cp.async.cg.shared.global [%0], [%1], 16;" :: "r"(saddr), "l"(gptr) : "memory")
#define CP_COMMIT() asm volatile("cp.async.commit_group;" ::: "memory")
#define CP_WAIT(n)  asm volatile("cp.async.wait_group %0;" :: "n"(n) : "memory")

#define LDS128(r, addr) \
    asm volatile("ld.shared.v4.b32 {%0,%1,%2,%3}, [%4];" \
        : "=r"((r)[0]), "=r"((r)[1]), "=r"((r)[2]), "=r"((r)[3]) : "r"(addr))
#define STS128(addr, r0, r1, r2, r3) \
    asm volatile("st.shared.v4.b32 [%0], {%1,%2,%3,%4};" \
        :: "r"(addr), "r"(r0), "r"(r1), "r"(r2), "r"(r3) : "memory")

// exact identity tanh: 1 - 2/(e^{2x}+1); abs err ~1e-7
__device__ __forceinline__ float fast_tanh(float x) {
    float e = __expf(2.0f * x);
    return 1.0f - __fdividef(2.0f, e + 1.0f);
}

// ---------------- weight prep: fp32 -> dense bf16 hi/lo [n][k] ----------------
__global__ void k_prep(const float* __restrict__ W1, const float* __restrict__ W2,
                       const float* __restrict__ Wa1)
{
    int mat = blockIdx.x;
    const float* W; int koff;
    if (mat == 0)      { W = W1;  koff = 0;   }
    else if (mat == 1) { W = W1;  koff = 128; }
    else if (mat == 2) { W = W2;  koff = 0;   }
    else               { W = Wa1; koff = 0;   }
    __nv_bfloat16* dh = (__nv_bfloat16*)(g_wsw + (size_t)mat * 65536);
    __nv_bfloat16* dl = dh + 16384;
    for (int idx = threadIdx.x; idx < 16384; idx += blockDim.x) {
        int n = idx >> 7, k = idx & 127;
        float w = W[(size_t)(koff + k) * 128 + n];   // B[n][k] = W[k][n]
        __nv_bfloat16 h = __float2bfloat16(w);
        __nv_bfloat16 l = __float2bfloat16(w - __bfloat162float(h));
        dh[n * 128 + k] = h;
        dl[n * 128 + k] = l;
    }
}

// ---------------- staging ----------------
__device__ __forceinline__ void stage_w_async(uint32_t smb, int mat, int tid) {
    const unsigned char* src = g_wsw + (size_t)mat * 65536;
    unsigned long long gbase = (unsigned long long)__cvta_generic_to_global((void*)src);
#pragma unroll
    for (int i = 0; i < 8; i++) {
        int idx = tid + i * 256;
        int r = idx >> 4, q = idx & 15;
        uint32_t soff = (uint32_t)(r * 136 + q * 8) * 2u;
        unsigned long long goff = (unsigned long long)(r * 128 + q * 8) * 2ull;
        CP_ASYNC16(smb + B_HI_OFF + soff,       gbase + goff);
        CP_ASYNC16(smb + B_HI_OFF + BLO + soff, gbase + 32768ull + goff);
    }
}

__device__ __forceinline__ uint32_t pack_hi(float a, float b, float& la, float& lb) {
    __nv_bfloat16 ha = __float2bfloat16(a), hb = __float2bfloat16(b);
    la = a - __bfloat162float(ha);
    lb = b - __bfloat162float(hb);
    return (uint32_t)__bfloat16_as_ushort(ha) | ((uint32_t)__bfloat16_as_ushort(hb) << 16);
}
__device__ __forceinline__ uint32_t pack_bf(float a, float b) {
    return (uint32_t)__bfloat16_as_ushort(__float2bfloat16(a)) |
           ((uint32_t)__bfloat16_as_ushort(__float2bfloat16(b)) << 16);
}

// ---------------- shared inner: 8 n16-tiles of B, 3-pass split MMA ----------------
__device__ __forceinline__ void mma_inner(uint32_t smb, uint32_t bRow, uint32_t bK0, int ks,
                                          const uint32_t* ah, const uint32_t* al,
                                          float (*acc)[4]) {
#pragma unroll
    for (int nt2 = 0; nt2 < 8; nt2++) {
        uint32_t bh[4], bl[4];
        uint32_t baddr = smb + B_HI_OFF +
            (bRow + (uint32_t)nt2 * (16u * 136u) + bK0 + (uint32_t)ks * 16u) * 2u;
        LDM4(bh, baddr);
        LDM4(bl, baddr + BLO);
        MMA16816(acc[2 * nt2],     ah, bh[0], bh[1]);
        MMA16816(acc[2 * nt2 + 1], ah, bh[2], bh[3]);
        MMA16816(acc[2 * nt2],     ah, bl[0], bl[1]);
        MMA16816(acc[2 * nt2 + 1], ah, bl[2], bl[3]);
        MMA16816(acc[2 * nt2],     al, bh[0], bh[1]);
        MMA16816(acc[2 * nt2 + 1], al, bh[2], bh[3]);
    }
}

// phase-1 block: A fragments straight from gmem x (every sector byte used)
__device__ __forceinline__ void mma_block_g(uint32_t smb, const float* __restrict__ x,
                                            size_t rowTile, int hh, int w, int L,
                                            float (*acc)[4]) {
    const int g = L >> 2, t = L & 3;
    const float* p0 = x + (rowTile + (size_t)(w * 16 + g)) * DIN + hh * 128 + 2 * t;
    const float* p1 = p0 + 8 * DIN;
    const int g3 = L >> 3, rr = L & 7;
    const uint32_t bRow = (uint32_t)((g3 >> 1) * 8 + rr) * 136u;
    const uint32_t bK0  = 8u * (uint32_t)(g3 & 1);
#pragma unroll 2
    for (int ks = 0; ks < 8; ks++) {
        float2 v0 = *(const float2*)(p0 + ks * 16);
        float2 v1 = *(const float2*)(p1 + ks * 16);
        float2 v2 = *(const float2*)(p0 + ks * 16 + 8);
        float2 v3 = *(const float2*)(p1 + ks * 16 + 8);
        uint32_t ah[4], al[4];
        float l0, l1;
        ah[0] = pack_hi(v0.x, v0.y, l0, l1); al[0] = pack_bf(l0, l1);
        ah[1] = pack_hi(v1.x, v1.y, l0, l1); al[1] = pack_bf(l0, l1);
        ah[2] = pack_hi(v2.x, v2.y, l0, l1); al[2] = pack_bf(l0, l1);
        ah[3] = pack_hi(v3.x, v3.y, l0, l1); al[3] = pack_bf(l0, l1);
        mma_inner(smb, bRow, bK0, ks, ah, al, acc);
    }
}

// phase-2/3 block: A hi from regs (afh), A lo from thread-private smem scratch
__device__ __forceinline__ void mma_block_r(uint32_t smb, const uint32_t* afh, int L, int tid,
                                            float (*acc)[4]) {
    const int g3 = L >> 3, rr = L & 7;
    const uint32_t bRow = (uint32_t)((g3 >> 1) * 8 + rr) * 136u;
    const uint32_t bK0  = 8u * (uint32_t)(g3 & 1);
#pragma unroll 2
    for (int ks = 0; ks < 8; ks++) {
        uint32_t al[4];
        LDS128(al, smb + SCR_OFF + (uint32_t)(ks * 256 + tid) * 16u);
        mma_inner(smb, bRow, bK0, ks, afh + ks * 4, al, acc);
    }
}

// repack C fragments (post-activation) into next-phase A fragments:
// hi -> afh regs, lo -> smem scratch (thread-private, no barrier needed)
__device__ __forceinline__ void repack_A(float (*acc)[4], uint32_t* afh, uint32_t smb, int tid) {
#pragma unroll
    for (int j = 0; j < 8; j++) {
        float l0, l1, l2, l3, m0, m1, m2, m3;
        uint32_t h0 = pack_hi(acc[2 * j][0],     acc[2 * j][1],     l0, l1);
        uint32_t h1 = pack_hi(acc[2 * j][2],     acc[2 * j][3],     l2, l3);
        uint32_t h2 = pack_hi(acc[2 * j + 1][0], acc[2 * j + 1][1], m0, m1);
        uint32_t h3 = pack_hi(acc[2 * j + 1][2], acc[2 * j + 1][3], m2, m3);
        afh[4 * j]     = h0;
        afh[4 * j + 1] = h1;
        afh[4 * j + 2] = h2;
        afh[4 * j + 3] = h3;
        STS128(smb + SCR_OFF + (uint32_t)(j * 256 + tid) * 16u,
               pack_bf(l0, l1), pack_bf(l2, l3), pack_bf(m0, m1), pack_bf(m2, m3));
    }
}

// ---------------- LN + ReLU epilogue (full row per warp, shuffle-only) ----------------
__device__ __forceinline__ void ln_relu(float (*acc)[4], const float* bias, int boff, int L) {
    const int q2 = 2 * (L & 3);
    float s0 = 0.f, s1 = 0.f;
#pragma unroll
    for (int nt = 0; nt < 16; nt++) {
        int c = nt * 8 + q2;
        float b0 = bias[boff + c], b1v = bias[boff + c + 1];
        acc[nt][0] += b0; acc[nt][1] += b1v; acc[nt][2] += b0; acc[nt][3] += b1v;
        s0 += acc[nt][0] + acc[nt][1];
        s1 += acc[nt][2] + acc[nt][3];
    }
    s0 += __shfl_xor_sync(0xffffffffu, s0, 1); s0 += __shfl_xor_sync(0xffffffffu, s0, 2);
    s1 += __shfl_xor_sync(0xffffffffu, s1, 1); s1 += __shfl_xor_sync(0xffffffffu, s1, 2);
    float mu0 = s0 * 0.0078125f, mu1 = s1 * 0.0078125f;
    float v0 = 0.f, v1 = 0.f;
#pragma unroll
    for (int nt = 0; nt < 16; nt++) {
        float d;
        d = acc[nt][0] - mu0; v0 = fmaf(d, d, v0);
        d = acc[nt][1] - mu0; v0 = fmaf(d, d, v0);
        d = acc[nt][2] - mu1; v1 = fmaf(d, d, v1);
        d = acc[nt][3] - mu1; v1 = fmaf(d, d, v1);
    }
    v0 += __shfl_xor_sync(0xffffffffu, v0, 1); v0 += __shfl_xor_sync(0xffffffffu, v0, 2);
    v1 += __shfl_xor_sync(0xffffffffu, v1, 1); v1 += __shfl_xor_sync(0xffffffffu, v1, 2);
    float i0 = rsqrtf(fmaf(v0, 0.0078125f, LN_EPS));
    float i1 = rsqrtf(fmaf(v1, 0.0078125f, LN_EPS));
#pragma unroll
    for (int nt = 0; nt < 16; nt++) {
        int c = nt * 8 + q2;
        float g0 = bias[boff + 128 + c], g1v = bias[boff + 128 + c + 1];
        float e0 = bias[boff + 256 + c], e1v = bias[boff + 256 + c + 1];
        acc[nt][0] = fmaxf(fmaf((acc[nt][0] - mu0) * i0, g0, e0), 0.f);
        acc[nt][1] = fmaxf(fmaf((acc[nt][1] - mu0) * i0, g1v, e1v), 0.f);
        acc[nt][2] = fmaxf(fmaf((acc[nt][2] - mu1) * i1, g0, e0), 0.f);
        acc[nt][3] = fmaxf(fmaf((acc[nt][3] - mu1) * i1, g1v, e1v), 0.f);
    }
}

// ---------------- fused row kernel (2 CTAs/SM) ----------------
__global__ void __launch_bounds__(256, 2)
k_rows_mma(const float* __restrict__ x,
           const float* __restrict__ b1, const float* __restrict__ g1, const float* __restrict__ be1,
           const float* __restrict__ b2, const float* __restrict__ g2, const float* __restrict__ be2,
           const float* __restrict__ ba1, const float* __restrict__ ba2, const float* __restrict__ Wa2)
{
    extern __shared__ char sm[];
    const uint32_t smb = smem_to_u32(sm);
    const int tid = threadIdx.x;
    const int w = tid >> 5, L = tid & 31;
    const size_t rowTile = (size_t)blockIdx.x * 128;
    float* bias = (float*)(sm + BIAS_OFF);

    stage_w_async(smb, 0, tid); CP_COMMIT();   // W1 half0

    if (tid < 128) {
        bias[tid]       = b1[tid];  bias[128 + tid] = g1[tid];  bias[256 + tid] = be1[tid];
        bias[384 + tid] = b2[tid];  bias[512 + tid] = g2[tid];  bias[640 + tid] = be2[tid];
        bias[768 + tid] = ba1[tid]; bias[896 + tid] = Wa2[tid];
    }
    if (tid == 0) bias[1024] = ba2[0];

    float acc[16][4];
#pragma unroll
    for (int nt = 0; nt < 16; nt++)
#pragma unroll
        for (int j = 0; j < 4; j++) acc[nt][j] = 0.f;

    // ===== PHASE 1: x @ W1 (K=256, two K=128 blocks; A from gmem) =====
    CP_WAIT(0);
    __syncthreads();
    mma_block_g(smb, x, rowTile, 0, w, L, acc);
    __syncthreads();
    stage_w_async(smb, 1, tid); CP_COMMIT();   // W1 half1
    CP_WAIT(0);
    __syncthreads();
    mma_block_g(smb, x, rowTile, 1, w, L, acc);
    __syncthreads();
    stage_w_async(smb, 2, tid); CP_COMMIT();   // W2 (overlaps LN1 epilogue)

    uint32_t afh[32];
    ln_relu(acc, bias, 0, L);
    repack_A(acc, afh, smb, tid);              // h1 -> A frags (regs + scratch)
    CP_WAIT(0);
    __syncthreads();

    // ===== PHASE 2: h1 @ W2 =====
#pragma unroll
    for (int nt = 0; nt < 16; nt++)
#pragma unroll
        for (int j = 0; j < 4; j++) acc[nt][j] = 0.f;
    mma_block_r(smb, afh, L, tid, acc);
    __syncthreads();
    stage_w_async(smb, 3, tid); CP_COMMIT();   // Wa1 (overlaps LN2 epilogue + h2 store)

    ln_relu(acc, bias, 384, L);
    // h2 -> gmem bf16, direct from fragments (all 32B sectors fully covered)
    {
        const int r0 = w * 16 + (L >> 2), r1 = r0 + 8;
        const int q2 = 2 * (L & 3);
        __nv_bfloat16* h0p = g_h2b + (rowTile + r0) * HDIM;
        __nv_bfloat16* h1p = g_h2b + (rowTile + r1) * HDIM;
#pragma unroll
        for (int nt = 0; nt < 16; nt++) {
            int c = nt * 8 + q2;
            *(uint32_t*)(h0p + c) = pack_bf(acc[nt][0], acc[nt][1]);
            *(uint32_t*)(h1p + c) = pack_bf(acc[nt][2], acc[nt][3]);
        }
    }
    repack_A(acc, afh, smb, tid);              // h2 -> A frags
    CP_WAIT(0);
    __syncthreads();

    // ===== PHASE 3: h2 @ Wa1 -> tanh -> dot Wa2 -> scores =====
#pragma unroll
    for (int nt = 0; nt < 16; nt++)
#pragma unroll
        for (int j = 0; j < 4; j++) acc[nt][j] = 0.f;
    mma_block_r(smb, afh, L, tid, acc);

    {
        const int r0 = w * 16 + (L >> 2), r1 = r0 + 8;
        const int q2 = 2 * (L & 3);
        float p0 = 0.f, p1 = 0.f;
#pragma unroll
        for (int nt = 0; nt < 16; nt++) {
            int c = nt * 8 + q2;
            float wa0 = bias[896 + c], wa1v = bias[896 + c + 1];
            float bb0 = bias[768 + c], bb1 = bias[768 + c + 1];
            p0 = fmaf(fast_tanh(acc[nt][0] + bb0), wa0, p0);
            p0 = fmaf(fast_tanh(acc[nt][1] + bb1), wa1v, p0);
            p1 = fmaf(fast_tanh(acc[nt][2] + bb0), wa0, p1);
            p1 = fmaf(fast_tanh(acc[nt][3] + bb1), wa1v, p1);
        }
        p0 += __shfl_xor_sync(0xffffffffu, p0, 1); p0 += __shfl_xor_sync(0xffffffffu, p0, 2);
        p1 += __shfl_xor_sync(0xffffffffu, p1, 1); p1 += __shfl_xor_sync(0xffffffffu, p1, 2);
        if ((L & 3) == 0) {
            float bb = bias[1024];
            g_scores[rowTile + r0] = p0 + bb;
            g_scores[rowTile + r1] = p1 + bb;
        }
    }
}

// ---------------- per-bag score max ----------------
__global__ __launch_bounds__(256)
void k_max()
{
    const int bag = blockIdx.x;
    const int tid = threadIdx.x;
    __shared__ float red[256];
    float m = -3.4e38f;
    const float* sp = g_scores + (size_t)bag * NPER;
    for (int i = tid; i < NPER; i += 256) m = fmaxf(m, sp[i]);
    red[tid] = m;
    __syncthreads();
    for (int off = 128; off; off >>= 1) {
        if (tid < off) red[tid] = fmaxf(red[tid], red[tid + off]);
        __syncthreads();
    }
    if (tid == 0) g_bagmax[bag] = red[0];
}

// ---------------- weighted partial sums (chunks of 512 rows, bf16 h2) ----------------
__global__ __launch_bounds__(256)
void k_wsum()
{
    const int b = blockIdx.x / NCHUNK2;
    const int c = blockIdx.x % NCHUNK2;
    const int tid = threadIdx.x;
    const int base = c * CHUNK;
    const int cnt = min(CHUNK, NPER - base);
    __shared__ float wrow[CHUNK];
    __shared__ float2 sred[256];

    const float bm = g_bagmax[b];
    {
        int i0 = tid, i1 = tid + 256;
        wrow[i0] = (i0 < cnt) ? expf((g_scores[(size_t)b * NPER + base + i0] - bm) * INV_TAU) : 0.f;
        wrow[i1] = (i1 < cnt) ? expf((g_scores[(size_t)b * NPER + base + i1] - bm) * INV_TAU) : 0.f;
    }
    __syncthreads();

    const int c2 = tid & 63;
    const int rg = tid >> 6;
    const uint32_t* hp = (const uint32_t*)(g_h2b + ((size_t)b * NPER + base) * HDIM) + c2;

    float2 a0 = {0.f,0.f}, a1 = {0.f,0.f}, a2 = {0.f,0.f}, a3 = {0.f,0.f};
    int n = rg;
    for (; n + 12 < cnt; n += 16) {
        uint32_t u0 = hp[(size_t)n * 64];
        uint32_t u1 = hp[(size_t)(n + 4) * 64];
        uint32_t u2 = hp[(size_t)(n + 8) * 64];
        uint32_t u3 = hp[(size_t)(n + 12) * 64];
        float2 f0 = __bfloat1622float2(*(const __nv_bfloat162*)&u0);
        float2 f1 = __bfloat1622float2(*(const __nv_bfloat162*)&u1);
        float2 f2 = __bfloat1622float2(*(const __nv_bfloat162*)&u2);
        float2 f3 = __bfloat1622float2(*(const __nv_bfloat162*)&u3);
        float w0 = wrow[n], w1 = wrow[n + 4], w2 = wrow[n + 8], w3 = wrow[n + 12];
        a0.x = fmaf(w0, f0.x, a0.x); a0.y = fmaf(w0, f0.y, a0.y);
        a1.x = fmaf(w1, f1.x, a1.x); a1.y = fmaf(w1, f1.y, a1.y);
        a2.x = fmaf(w2, f2.x, a2.x); a2.y = fmaf(w2, f2.y, a2.y);
        a3.x = fmaf(w3, f3.x, a3.x); a3.y = fmaf(w3, f3.y, a3.y);
    }
    for (; n < cnt; n += 4) {
        uint32_t u = hp[(size_t)n * 64];
        float2 f = __bfloat1622float2(*(const __nv_bfloat162*)&u);
        float wv = wrow[n];
        a0.x = fmaf(wv, f.x, a0.x); a0.y = fmaf(wv, f.y, a0.y);
    }
    float2 at;
    at.x = (a0.x + a1.x) + (a2.x + a3.x);
    at.y = (a0.y + a1.y) + (a2.y + a3.y);
    sred[tid] = at;
    __syncthreads();
    if (tid < 64) {
        float2 t0 = sred[tid], t1 = sred[tid + 64], t2 = sred[tid + 128], t3 = sred[tid + 192];
        float* pv = g_pvec + ((size_t)b * NCHUNK2 + c) * HDIM;
        pv[2 * tid]     = (t0.x + t1.x) + (t2.x + t3.x);
        pv[2 * tid + 1] = (t0.y + t1.y) + (t2.y + t3.y);
    }

    __syncthreads();
    float z = wrow[tid] + wrow[tid + 256];
    wrow[tid] = z;
    __syncthreads();
    for (int off = 128; off; off >>= 1) {
        if (tid < off) wrow[tid] += wrow[tid + off];
        __syncthreads();
    }
    if (tid == 0) g_pZ[b * NCHUNK2 + c] = wrow[0];
}

// ---------------- final heads ----------------
__global__ __launch_bounds__(128)
void k_final(const float* __restrict__ Wc1, const float* __restrict__ bc1,
             const float* __restrict__ Wc2, const float* __restrict__ bc2,
             const float* __restrict__ Ws1, const float* __restrict__ bs1,
             const float* __restrict__ Ws2, const float* __restrict__ bs2,
             float* __restrict__ out)
{
    const int bag = blockIdx.x;
    const int tid = threadIdx.x;
    __shared__ float bagn[128];
    __shared__ float hid[128];
    __shared__ float redz[128];
    __shared__ float hs[64];

    float vv = 0.0f;
    for (int c = 0; c < NCHUNK2; c++)
        vv += g_pvec[((size_t)bag * NCHUNK2 + c) * HDIM + tid];

    float zp = 0.0f;
    for (int c = tid; c < NCHUNK2; c += 128)
        zp += g_pZ[bag * NCHUNK2 + c];
    redz[tid] = zp;
    __syncthreads();
    for (int off = 64; off; off >>= 1) {
        if (tid < off) redz[tid] += redz[tid + off];
        __syncthreads();
    }
    const float Z = redz[0];
    bagn[tid] = vv / Z;
    __syncthreads();

    {
        float h = bc1[tid];
        for (int k = 0; k < 128; k++) h = fmaf(bagn[k], Wc1[k * 128 + tid], h);
        hid[tid] = fmaxf(h, 0.0f);
    }
    if (tid < 64) {
        float h = bs1[tid];
        for (int k = 0; k < 128; k++) h = fmaf(bagn[k], Ws1[k * 64 + tid], h);
        hs[tid] = fmaxf(h, 0.0f);
    }
    __syncthreads();

    if (tid < 2) {
        float s = bc2[tid];
        for (int j = 0; j < 128; j++) s = fmaf(hid[j], Wc2[j * 2 + tid], s);
        out[bag * 2 + tid] = s;
    }
    if (tid == 2) {
        float r = bs2[0];
        for (int j = 0; j < 64; j++) r = fmaf(hs[j], Ws2[j], r);
        out[16 + bag] = r;
    }
}

extern "C" void kernel_launch(void* const* d_in, const int* in_sizes, int n_in,
                              void* d_out, int out_size)
{
    const float* x   = (const float*)d_in[0];
    const float* W1  = (const float*)d_in[1];
    const float* b1  = (const float*)d_in[2];
    const float* g1  = (const float*)d_in[3];
    const float* be1 = (const float*)d_in[4];
    const float* W2  = (const float*)d_in[5];
    const float* b2  = (const float*)d_in[6];
    const float* g2  = (const float*)d_in[7];
    const float* be2 = (const float*)d_in[8];
    const float* Wa1 = (const float*)d_in[9];
    const float* ba1 = (const float*)d_in[10];
    const float* Wa2 = (const float*)d_in[11];
    const float* ba2 = (const float*)d_in[12];
    const float* Wc1 = (const float*)d_in[13];
    const float* bc1 = (const float*)d_in[14];
    const float* Wc2 = (const float*)d_in[15];
    const float* bc2 = (const float*)d_in[16];
    const float* Ws1 = (const float*)d_in[17];
    const float* bs1 = (const float*)d_in[18];
    const float* Ws2 = (const float*)d_in[19];
    const float* bs2 = (const float*)d_in[20];
    float* out = (float*)d_out;

    cudaFuncSetAttribute(k_rows_mma, cudaFuncAttributeMaxDynamicSharedMemorySize, SMEM_SZ);

    k_prep<<<4, 256>>>(W1, W2, Wa1);
    k_rows_mma<<<MROWS / 128, 256, SMEM_SZ>>>(x, b1, g1, be1, b2, g2, be2, ba1, ba2, Wa2);
    k_max<<<NBAG, 256>>>();
    k_wsum<<<NBAG * NCHUNK2, 256>>>();
    k_final<<<NBAG, 128>>>(Wc1, bc1, Wc2, bc2, Ws1, bs1, Ws2, bs2, out);
}

// round 9
// speedup vs baseline: 1.4523x; 1.2257x over previous
#include <cuda_runtime.h>
#include <cuda_bf16.h>
#include <cuda_fp16.h>
#include <math.h>
#include <stdint.h>

// ---------------- problem constants ----------------
#define MROWS   400000
#define NBAG    8
#define NPER    50000
#define DIN     256
#define HDIM    128
#define INV_TAU (1.0f/0.3f)
#define LN_EPS  1e-5f
#define CHUNK   512
#define NCHUNK2 98               // ceil(50000/512)

// ---------------- scratch globals ----------------
__device__ __nv_bfloat16 g_h2b[(size_t)MROWS * HDIM];   // 102.4 MB (bf16)
__device__ float g_scores[MROWS];
__device__ float g_bagmax[NBAG];
__device__ float g_pvec[NBAG * NCHUNK2 * HDIM];
__device__ float g_pZ[NBAG * NCHUNK2];
// fp16 hi/lo weights, dense [n][k]: [W1half0, W1half1, W2, Wa1] x [hi 32KB | lo 32KB]
__device__ __align__(16) unsigned char g_wsw[4 * 65536];

// ---------------- smem layout (bytes), single CTA = 73744 -> 2 CTAs/SM ----------------
#define B_HI_OFF  0              // weight buffer hi [128][136] fp16
#define BLO       34816          // hi -> lo offset
#define BIAS_OFF  69632          // 1025 floats
#define SMEM_SZ   73744

__device__ __forceinline__ uint32_t smem_to_u32(const void* p) {
    uint32_t a;
    asm("{ .reg .u64 t; cvta.to.shared.u64 t, %1; cvt.u32.u64 %0, t; }" : "=r"(a) : "l"(p));
    return a;
}

#define LDM4(r, addr) \
    asm volatile("ldmatrix.sync.aligned.m8n8.x4.shared.b16 {%0,%1,%2,%3}, [%4];" \
        : "=r"((r)[0]), "=r"((r)[1]), "=r"((r)[2]), "=r"((r)[3]) : "r"(addr))

#define MMA16816(c, a, b0, b1) \
    asm volatile("mma.sync.aligned.m16n8k16.row.col.f32.f16.f16.f32 " \
        "{%0,%1,%2,%3}, {%4,%5,%6,%7}, {%8,%9}, {%0,%1,%2,%3};" \
        : "+f"((c)[0]), "+f"((c)[1]), "+f"((c)[2]), "+f"((c)[3]) \
        : "r"((a)[0]), "r"((a)[1]), "r"((a)[2]), "r"((a)[3]), "r"(b0), "r"(b1))

#define CP_ASYNC16(saddr, gptr) \
    asm volatile("cp.async.cg.shared.global [%0], [%1], 16;" :: "r"(saddr), "l"(gptr) : "memory")
#define CP_COMMIT() asm volatile("cp.async.commit_group;" ::: "memory")
#define CP_WAIT(n)  asm volatile("cp.async.wait_group %0;" :: "n"(n) : "memory")

// exact identity tanh: 1 - 2/(e^{2x}+1); abs err ~1e-7
__device__ __forceinline__ float fast_tanh(float x) {
    float e = __expf(2.0f * x);
    return 1.0f - __fdividef(2.0f, e + 1.0f);
}

__device__ __forceinline__ uint32_t pack_h2(float a, float b) {
    __half2 h = __floats2half2_rn(a, b);
    return *(uint32_t*)&h;
}
__device__ __forceinline__ uint32_t pack_bf(float a, float b) {
    return (uint32_t)__bfloat16_as_ushort(__float2bfloat16(a)) |
           ((uint32_t)__bfloat16_as_ushort(__float2bfloat16(b)) << 16);
}

// ---------------- weight prep: fp32 -> dense fp16 hi/lo [n][k] ----------------
__global__ void k_prep(const float* __restrict__ W1, const float* __restrict__ W2,
                       const float* __restrict__ Wa1)
{
    int mat = blockIdx.x;
    const float* W; int koff;
    if (mat == 0)      { W = W1;  koff = 0;   }
    else if (mat == 1) { W = W1;  koff = 128; }
    else if (mat == 2) { W = W2;  koff = 0;   }
    else               { W = Wa1; koff = 0;   }
    __half* dh = (__half*)(g_wsw + (size_t)mat * 65536);
    __half* dl = dh + 16384;
    for (int idx = threadIdx.x; idx < 16384; idx += blockDim.x) {
        int n = idx >> 7, k = idx & 127;
        float w = W[(size_t)(koff + k) * 128 + n];   // B[n][k] = W[k][n]
        __half h = __float2half_rn(w);
        __half l = __float2half_rn(w - __half2float(h));
        dh[n * 128 + k] = h;
        dl[n * 128 + k] = l;
    }
}

// ---------------- staging ----------------
__device__ __forceinline__ void stage_w_async(uint32_t smb, int mat, int tid) {
    const unsigned char* src = g_wsw + (size_t)mat * 65536;
    unsigned long long gbase = (unsigned long long)__cvta_generic_to_global((void*)src);
#pragma unroll
    for (int i = 0; i < 8; i++) {
        int idx = tid + i * 256;
        int r = idx >> 4, q = idx & 15;
        uint32_t soff = (uint32_t)(r * 136 + q * 8) * 2u;
        unsigned long long goff = (unsigned long long)(r * 128 + q * 8) * 2ull;
        CP_ASYNC16(smb + B_HI_OFF + soff,       gbase + goff);
        CP_ASYNC16(smb + B_HI_OFF + BLO + soff, gbase + 32768ull + goff);
    }
}

// ---------------- shared inner: 8 n16-tiles of B, 2-pass (B hi + B lo) ----------------
__device__ __forceinline__ void mma_inner(uint32_t smb, uint32_t bRow, uint32_t bK0, int ks,
                                          const uint32_t* a, float (*acc)[4]) {
#pragma unroll
    for (int nt2 = 0; nt2 < 8; nt2++) {
        uint32_t bh[4], bl[4];
        uint32_t baddr = smb + B_HI_OFF +
            (bRow + (uint32_t)nt2 * (16u * 136u) + bK0 + (uint32_t)ks * 16u) * 2u;
        LDM4(bh, baddr);
        LDM4(bl, baddr + BLO);
        MMA16816(acc[2 * nt2],     a, bh[0], bh[1]);
        MMA16816(acc[2 * nt2 + 1], a, bh[2], bh[3]);
        MMA16816(acc[2 * nt2],     a, bl[0], bl[1]);
        MMA16816(acc[2 * nt2 + 1], a, bl[2], bl[3]);
    }
}

// phase-1 block: A fragments straight from gmem x (every sector byte used)
__device__ __forceinline__ void mma_block_g(uint32_t smb, const float* __restrict__ x,
                                            size_t rowTile, int hh, int w, int L,
                                            float (*acc)[4]) {
    const int g = L >> 2, t = L & 3;
    const float* p0 = x + (rowTile + (size_t)(w * 16 + g)) * DIN + hh * 128 + 2 * t;
    const float* p1 = p0 + 8 * DIN;
    const int g3 = L >> 3, rr = L & 7;
    const uint32_t bRow = (uint32_t)((g3 >> 1) * 8 + rr) * 136u;
    const uint32_t bK0  = 8u * (uint32_t)(g3 & 1);
#pragma unroll 2
    for (int ks = 0; ks < 8; ks++) {
        float2 v0 = *(const float2*)(p0 + ks * 16);
        float2 v1 = *(const float2*)(p1 + ks * 16);
        float2 v2 = *(const float2*)(p0 + ks * 16 + 8);
        float2 v3 = *(const float2*)(p1 + ks * 16 + 8);
        uint32_t a[4];
        a[0] = pack_h2(v0.x, v0.y);
        a[1] = pack_h2(v1.x, v1.y);
        a[2] = pack_h2(v2.x, v2.y);
        a[3] = pack_h2(v3.x, v3.y);
        mma_inner(smb, bRow, bK0, ks, a, acc);
    }
}

// phase-2/3 block: A entirely from regs (afh)
__device__ __forceinline__ void mma_block_r(uint32_t smb, const uint32_t* afh, int L,
                                            float (*acc)[4]) {
    const int g3 = L >> 3, rr = L & 7;
    const uint32_t bRow = (uint32_t)((g3 >> 1) * 8 + rr) * 136u;
    const uint32_t bK0  = 8u * (uint32_t)(g3 & 1);
#pragma unroll 2
    for (int ks = 0; ks < 8; ks++)
        mma_inner(smb, bRow, bK0, ks, afh + ks * 4, acc);
}

// repack C fragments (post-activation) into next-phase A fragments (fp16, regs only)
__device__ __forceinline__ void repack_A(float (*acc)[4], uint32_t* afh) {
#pragma unroll
    for (int j = 0; j < 8; j++) {
        afh[4 * j]     = pack_h2(acc[2 * j][0],     acc[2 * j][1]);
        afh[4 * j + 1] = pack_h2(acc[2 * j][2],     acc[2 * j][3]);
        afh[4 * j + 2] = pack_h2(acc[2 * j + 1][0], acc[2 * j + 1][1]);
        afh[4 * j + 3] = pack_h2(acc[2 * j + 1][2], acc[2 * j + 1][3]);
    }
}

// ---------------- LN + ReLU epilogue (full row per warp, shuffle-only) ----------------
__device__ __forceinline__ void ln_relu(float (*acc)[4], const float* bias, int boff, int L) {
    const int q2 = 2 * (L & 3);
    float s0 = 0.f, s1 = 0.f;
#pragma unroll
    for (int nt = 0; nt < 16; nt++) {
        int c = nt * 8 + q2;
        float b0 = bias[boff + c], b1v = bias[boff + c + 1];
        acc[nt][0] += b0; acc[nt][1] += b1v; acc[nt][2] += b0; acc[nt][3] += b1v;
        s0 += acc[nt][0] + acc[nt][1];
        s1 += acc[nt][2] + acc[nt][3];
    }
    s0 += __shfl_xor_sync(0xffffffffu, s0, 1); s0 += __shfl_xor_sync(0xffffffffu, s0, 2);
    s1 += __shfl_xor_sync(0xffffffffu, s1, 1); s1 += __shfl_xor_sync(0xffffffffu, s1, 2);
    float mu0 = s0 * 0.0078125f, mu1 = s1 * 0.0078125f;
    float v0 = 0.f, v1 = 0.f;
#pragma unroll
    for (int nt = 0; nt < 16; nt++) {
        float d;
        d = acc[nt][0] - mu0; v0 = fmaf(d, d, v0);
        d = acc[nt][1] - mu0; v0 = fmaf(d, d, v0);
        d = acc[nt][2] - mu1; v1 = fmaf(d, d, v1);
        d = acc[nt][3] - mu1; v1 = fmaf(d, d, v1);
    }
    v0 += __shfl_xor_sync(0xffffffffu, v0, 1); v0 += __shfl_xor_sync(0xffffffffu, v0, 2);
    v1 += __shfl_xor_sync(0xffffffffu, v1, 1); v1 += __shfl_xor_sync(0xffffffffu, v1, 2);
    float i0 = rsqrtf(fmaf(v0, 0.0078125f, LN_EPS));
    float i1 = rsqrtf(fmaf(v1, 0.0078125f, LN_EPS));
#pragma unroll
    for (int nt = 0; nt < 16; nt++) {
        int c = nt * 8 + q2;
        float g0 = bias[boff + 128 + c], g1v = bias[boff + 128 + c + 1];
        float e0 = bias[boff + 256 + c], e1v = bias[boff + 256 + c + 1];
        acc[nt][0] = fmaxf(fmaf((acc[nt][0] - mu0) * i0, g0, e0), 0.f);
        acc[nt][1] = fmaxf(fmaf((acc[nt][1] - mu0) * i0, g1v, e1v), 0.f);
        acc[nt][2] = fmaxf(fmaf((acc[nt][2] - mu1) * i1, g0, e0), 0.f);
        acc[nt][3] = fmaxf(fmaf((acc[nt][3] - mu1) * i1, g1v, e1v), 0.f);
    }
}

// ---------------- fused row kernel (2 CTAs/SM) ----------------
__global__ void __launch_bounds__(256, 2)
k_rows_mma(const float* __restrict__ x,
           const float* __restrict__ b1, const float* __restrict__ g1, const float* __restrict__ be1,
           const float* __restrict__ b2, const float* __restrict__ g2, const float* __restrict__ be2,
           const float* __restrict__ ba1, const float* __restrict__ ba2, const float* __restrict__ Wa2)
{
    extern __shared__ char sm[];
    const uint32_t smb = smem_to_u32(sm);
    const int tid = threadIdx.x;
    const int w = tid >> 5, L = tid & 31;
    const size_t rowTile = (size_t)blockIdx.x * 128;
    float* bias = (float*)(sm + BIAS_OFF);

    stage_w_async(smb, 0, tid); CP_COMMIT();   // W1 half0

    if (tid < 128) {
        bias[tid]       = b1[tid];  bias[128 + tid] = g1[tid];  bias[256 + tid] = be1[tid];
        bias[384 + tid] = b2[tid];  bias[512 + tid] = g2[tid];  bias[640 + tid] = be2[tid];
        bias[768 + tid] = ba1[tid]; bias[896 + tid] = Wa2[tid];
    }
    if (tid == 0) bias[1024] = ba2[0];

    float acc[16][4];
#pragma unroll
    for (int nt = 0; nt < 16; nt++)
#pragma unroll
        for (int j = 0; j < 4; j++) acc[nt][j] = 0.f;

    // ===== PHASE 1: x @ W1 (K=256, two K=128 blocks; A from gmem) =====
    CP_WAIT(0);
    __syncthreads();
    mma_block_g(smb, x, rowTile, 0, w, L, acc);
    __syncthreads();
    stage_w_async(smb, 1, tid); CP_COMMIT();   // W1 half1
    CP_WAIT(0);
    __syncthreads();
    mma_block_g(smb, x, rowTile, 1, w, L, acc);
    __syncthreads();
    stage_w_async(smb, 2, tid); CP_COMMIT();   // W2 (overlaps LN1 epilogue)

    uint32_t afh[32];
    ln_relu(acc, bias, 0, L);
    repack_A(acc, afh);                        // h1 -> A frags (regs only)
    CP_WAIT(0);
    __syncthreads();

    // ===== PHASE 2: h1 @ W2 =====
#pragma unroll
    for (int nt = 0; nt < 16; nt++)
#pragma unroll
        for (int j = 0; j < 4; j++) acc[nt][j] = 0.f;
    mma_block_r(smb, afh, L, acc);
    __syncthreads();
    stage_w_async(smb, 3, tid); CP_COMMIT();   // Wa1 (overlaps LN2 epilogue + h2 store)

    ln_relu(acc, bias, 384, L);
    // h2 -> gmem bf16, direct from fragments (all 32B sectors fully covered)
    {
        const int r0 = w * 16 + (L >> 2), r1 = r0 + 8;
        const int q2 = 2 * (L & 3);
        __nv_bfloat16* h0p = g_h2b + (rowTile + r0) * HDIM;
        __nv_bfloat16* h1p = g_h2b + (rowTile + r1) * HDIM;
#pragma unroll
        for (int nt = 0; nt < 16; nt++) {
            int c = nt * 8 + q2;
            *(uint32_t*)(h0p + c) = pack_bf(acc[nt][0], acc[nt][1]);
            *(uint32_t*)(h1p + c) = pack_bf(acc[nt][2], acc[nt][3]);
        }
    }
    repack_A(acc, afh);                        // h2 -> A frags
    CP_WAIT(0);
    __syncthreads();

    // ===== PHASE 3: h2 @ Wa1 -> tanh -> dot Wa2 -> scores =====
#pragma unroll
    for (int nt = 0; nt < 16; nt++)
#pragma unroll
        for (int j = 0; j < 4; j++) acc[nt][j] = 0.f;
    mma_block_r(smb, afh, L, acc);

    {
        const int r0 = w * 16 + (L >> 2), r1 = r0 + 8;
        const int q2 = 2 * (L & 3);
        float p0 = 0.f, p1 = 0.f;
#pragma unroll
        for (int nt = 0; nt < 16; nt++) {
            int c = nt * 8 + q2;
            float wa0 = bias[896 + c], wa1v = bias[896 + c + 1];
            float bb0 = bias[768 + c], bb1 = bias[768 + c + 1];
            p0 = fmaf(fast_tanh(acc[nt][0] + bb0), wa0, p0);
            p0 = fmaf(fast_tanh(acc[nt][1] + bb1), wa1v, p0);
            p1 = fmaf(fast_tanh(acc[nt][2] + bb0), wa0, p1);
            p1 = fmaf(fast_tanh(acc[nt][3] + bb1), wa1v, p1);
        }
        p0 += __shfl_xor_sync(0xffffffffu, p0, 1); p0 += __shfl_xor_sync(0xffffffffu, p0, 2);
        p1 += __shfl_xor_sync(0xffffffffu, p1, 1); p1 += __shfl_xor_sync(0xffffffffu, p1, 2);
        if ((L & 3) == 0) {
            float bb = bias[1024];
            g_scores[rowTile + r0] = p0 + bb;
            g_scores[rowTile + r1] = p1 + bb;
        }
    }
}

// ---------------- per-bag score max ----------------
__global__ __launch_bounds__(256)
void k_max()
{
    const int bag = blockIdx.x;
    const int tid = threadIdx.x;
    __shared__ float red[256];
    float m = -3.4e38f;
    const float* sp = g_scores + (size_t)bag * NPER;
    for (int i = tid; i < NPER; i += 256) m = fmaxf(m, sp[i]);
    red[tid] = m;
    __syncthreads();
    for (int off = 128; off; off >>= 1) {
        if (tid < off) red[tid] = fmaxf(red[tid], red[tid + off]);
        __syncthreads();
    }
    if (tid == 0) g_bagmax[bag] = red[0];
}

// ---------------- weighted partial sums (chunks of 512 rows, bf16 h2) ----------------
__global__ __launch_bounds__(256)
void k_wsum()
{
    const int b = blockIdx.x / NCHUNK2;
    const int c = blockIdx.x % NCHUNK2;
    const int tid = threadIdx.x;
    const int base = c * CHUNK;
    const int cnt = min(CHUNK, NPER - base);
    __shared__ float wrow[CHUNK];
    __shared__ float2 sred[256];

    const float bm = g_bagmax[b];
    {
        int i0 = tid, i1 = tid + 256;
        wrow[i0] = (i0 < cnt) ? expf((g_scores[(size_t)b * NPER + base + i0] - bm) * INV_TAU) : 0.f;
        wrow[i1] = (i1 < cnt) ? expf((g_scores[(size_t)b * NPER + base + i1] - bm) * INV_TAU) : 0.f;
    }
    __syncthreads();

    const int c2 = tid & 63;
    const int rg = tid >> 6;
    const uint32_t* hp = (const uint32_t*)(g_h2b + ((size_t)b * NPER + base) * HDIM) + c2;

    float2 a0 = {0.f,0.f}, a1 = {0.f,0.f}, a2 = {0.f,0.f}, a3 = {0.f,0.f};
    int n = rg;
    for (; n + 12 < cnt; n += 16) {
        uint32_t u0 = hp[(size_t)n * 64];
        uint32_t u1 = hp[(size_t)(n + 4) * 64];
        uint32_t u2 = hp[(size_t)(n + 8) * 64];
        uint32_t u3 = hp[(size_t)(n + 12) * 64];
        float2 f0 = __bfloat1622float2(*(const __nv_bfloat162*)&u0);
        float2 f1 = __bfloat1622float2(*(const __nv_bfloat162*)&u1);
        float2 f2 = __bfloat1622float2(*(const __nv_bfloat162*)&u2);
        float2 f3 = __bfloat1622float2(*(const __nv_bfloat162*)&u3);
        float w0 = wrow[n], w1 = wrow[n + 4], w2 = wrow[n + 8], w3 = wrow[n + 12];
        a0.x = fmaf(w0, f0.x, a0.x); a0.y = fmaf(w0, f0.y, a0.y);
        a1.x = fmaf(w1, f1.x, a1.x); a1.y = fmaf(w1, f1.y, a1.y);
        a2.x = fmaf(w2, f2.x, a2.x); a2.y = fmaf(w2, f2.y, a2.y);
        a3.x = fmaf(w3, f3.x, a3.x); a3.y = fmaf(w3, f3.y, a3.y);
    }
    for (; n < cnt; n += 4) {
        uint32_t u = hp[(size_t)n * 64];
        float2 f = __bfloat1622float2(*(const __nv_bfloat162*)&u);
        float wv = wrow[n];
        a0.x = fmaf(wv, f.x, a0.x); a0.y = fmaf(wv, f.y, a0.y);
    }
    float2 at;
    at.x = (a0.x + a1.x) + (a2.x + a3.x);
    at.y = (a0.y + a1.y) + (a2.y + a3.y);
    sred[tid] = at;
    __syncthreads();
    if (tid < 64) {
        float2 t0 = sred[tid], t1 = sred[tid + 64], t2 = sred[tid + 128], t3 = sred[tid + 192];
        float* pv = g_pvec + ((size_t)b * NCHUNK2 + c) * HDIM;
        pv[2 * tid]     = (t0.x + t1.x) + (t2.x + t3.x);
        pv[2 * tid + 1] = (t0.y + t1.y) + (t2.y + t3.y);
    }

    __syncthreads();
    float z = wrow[tid] + wrow[tid + 256];
    wrow[tid] = z;
    __syncthreads();
    for (int off = 128; off; off >>= 1) {
        if (tid < off) wrow[tid] += wrow[tid + off];
        __syncthreads();
    }
    if (tid == 0) g_pZ[b * NCHUNK2 + c] = wrow[0];
}

// ---------------- final heads ----------------
__global__ __launch_bounds__(128)
void k_final(const float* __restrict__ Wc1, const float* __restrict__ bc1,
             const float* __restrict__ Wc2, const float* __restrict__ bc2,
             const float* __restrict__ Ws1, const float* __restrict__ bs1,
             const float* __restrict__ Ws2, const float* __restrict__ bs2,
             float* __restrict__ out)
{
    const int bag = blockIdx.x;
    const int tid = threadIdx.x;
    __shared__ float bagn[128];
    __shared__ float hid[128];
    __shared__ float redz[128];
    __shared__ float hs[64];

    float vv = 0.0f;
    for (int c = 0; c < NCHUNK2; c++)
        vv += g_pvec[((size_t)bag * NCHUNK2 + c) * HDIM + tid];

    float zp = 0.0f;
    for (int c = tid; c < NCHUNK2; c += 128)
        zp += g_pZ[bag * NCHUNK2 + c];
    redz[tid] = zp;
    __syncthreads();
    for (int off = 64; off; off >>= 1) {
        if (tid < off) redz[tid] += redz[tid + off];
        __syncthreads();
    }
    const float Z = redz[0];
    bagn[tid] = vv / Z;
    __syncthreads();

    {
        float h = bc1[tid];
        for (int k = 0; k < 128; k++) h = fmaf(bagn[k], Wc1[k * 128 + tid], h);
        hid[tid] = fmaxf(h, 0.0f);
    }
    if (tid < 64) {
        float h = bs1[tid];
        for (int k = 0; k < 128; k++) h = fmaf(bagn[k], Ws1[k * 64 + tid], h);
        hs[tid] = fmaxf(h, 0.0f);
    }
    __syncthreads();

    if (tid < 2) {
        float s = bc2[tid];
        for (int j = 0; j < 128; j++) s = fmaf(hid[j], Wc2[j * 2 + tid], s);
        out[bag * 2 + tid] = s;
    }
    if (tid == 2) {
        float r = bs2[0];
        for (int j = 0; j < 64; j++) r = fmaf(hs[j], Ws2[j], r);
        out[16 + bag] = r;
    }
}

extern "C" void kernel_launch(void* const* d_in, const int* in_sizes, int n_in,
                              void* d_out, int out_size)
{
    const float* x   = (const float*)d_in[0];
    const float* W1  = (const float*)d_in[1];
    const float* b1  = (const float*)d_in[2];
    const float* g1  = (const float*)d_in[3];
    const float* be1 = (const float*)d_in[4];
    const float* W2  = (const float*)d_in[5];
    const float* b2  = (const float*)d_in[6];
    const float* g2  = (const float*)d_in[7];
    const float* be2 = (const float*)d_in[8];
    const float* Wa1 = (const float*)d_in[9];
    const float* ba1 = (const float*)d_in[10];
    const float* Wa2 = (const float*)d_in[11];
    const float* ba2 = (const float*)d_in[12];
    const float* Wc1 = (const float*)d_in[13];
    const float* bc1 = (const float*)d_in[14];
    const float* Wc2 = (const float*)d_in[15];
    const float* bc2 = (const float*)d_in[16];
    const float* Ws1 = (const float*)d_in[17];
    const float* bs1 = (const float*)d_in[18];
    const float* Ws2 = (const float*)d_in[19];
    const float* bs2 = (const float*)d_in[20];
    float* out = (float*)d_out;

    cudaFuncSetAttribute(k_rows_mma, cudaFuncAttributeMaxDynamicSharedMemorySize, SMEM_SZ);

    k_prep<<<4, 256>>>(W1, W2, Wa1);
    k_rows_mma<<<MROWS / 128, 256, SMEM_SZ>>>(x, b1, g1, be1, b2, g2, be2, ba1, ba2, Wa2);
    k_max<<<NBAG, 256>>>();
    k_wsum<<<NBAG * NCHUNK2, 256>>>();
    k_final<<<NBAG, 128>>>(Wc1, bc1, Wc2, bc2, Ws1, bs1, Ws2, bs2, out);
}

// round 10
// speedup vs baseline: 1.5848x; 1.0912x over previous
#include <cuda_runtime.h>
#include <cuda_bf16.h>
#include <cuda_fp16.h>
#include <math.h>
#include <stdint.h>

// ---------------- problem constants ----------------
#define MROWS   400000
#define NBAG    8
#define NPER    50000
#define DIN     256
#define HDIM    128
#define INV_TAU (1.0f/0.3f)
#define LN_EPS  1e-5f
#define CHUNK   512
#define NCHUNK2 98               // ceil(50000/512)

// ---------------- scratch globals ----------------
__device__ __nv_bfloat16 g_h2b[(size_t)MROWS * HDIM];   // 102.4 MB (bf16)
__device__ float g_scores[MROWS];
__device__ float g_bagmax[NBAG];
__device__ float g_pvec[NBAG * NCHUNK2 * HDIM];
__device__ float g_pZ[NBAG * NCHUNK2];
// fp16 hi/lo weights, dense [n][k]: [W1half0, W1half1, W2, Wa1] x [hi 32KB | lo 32KB]
__device__ __align__(16) unsigned char g_wsw[4 * 65536];

// ---------------- smem layout (bytes), single CTA = 73744 -> 2 CTAs/SM ----------------
#define B_HI_OFF  0              // weight buffer hi [128][136] fp16
#define BLO       34816          // hi -> lo offset
#define BIAS_OFF  69632          // 1025 floats
#define SMEM_SZ   73744

__device__ __forceinline__ uint32_t smem_to_u32(const void* p) {
    uint32_t a;
    asm("{ .reg .u64 t; cvta.to.shared.u64 t, %1; cvt.u32.u64 %0, t; }" : "=r"(a) : "l"(p));
    return a;
}

#define LDM4(r, addr) \
    asm volatile("ldmatrix.sync.aligned.m8n8.x4.shared.b16 {%0,%1,%2,%3}, [%4];" \
        : "=r"((r)[0]), "=r"((r)[1]), "=r"((r)[2]), "=r"((r)[3]) : "r"(addr))

#define MMA16816(c, a, b0, b1) \
    asm volatile("mma.sync.aligned.m16n8k16.row.col.f32.f16.f16.f32 " \
        "{%0,%1,%2,%3}, {%4,%5,%6,%7}, {%8,%9}, {%0,%1,%2,%3};" \
        : "+f"((c)[0]), "+f"((c)[1]), "+f"((c)[2]), "+f"((c)[3]) \
        : "r"((a)[0]), "r"((a)[1]), "r"((a)[2]), "r"((a)[3]), "r"(b0), "r"(b1))

#define CP_ASYNC16(saddr, gptr) \
    asm volatile("cp.async.cg.shared.global [%0], [%1], 16;" :: "r"(saddr), "l"(gptr) : "memory")
#define CP_COMMIT() asm volatile("cp.async.commit_group;" ::: "memory")
#define CP_WAIT(n)  asm volatile("cp.async.wait_group %0;" :: "n"(n) : "memory")

// exact identity tanh: 1 - 2/(e^{2x}+1); abs err ~1e-7
__device__ __forceinline__ float fast_tanh(float x) {
    float e = __expf(2.0f * x);
    return 1.0f - __fdividef(2.0f, e + 1.0f);
}

__device__ __forceinline__ uint32_t pack_h2(float a, float b) {
    __half2 h = __floats2half2_rn(a, b);
    return *(uint32_t*)&h;
}
__device__ __forceinline__ uint32_t pack_bf(float a, float b) {
    return (uint32_t)__bfloat16_as_ushort(__float2bfloat16(a)) |
           ((uint32_t)__bfloat16_as_ushort(__float2bfloat16(b)) << 16);
}

// ---------------- weight prep: fp32 -> dense fp16 hi/lo [n][k] ----------------
__global__ void k_prep(const float* __restrict__ W1, const float* __restrict__ W2,
                       const float* __restrict__ Wa1)
{
    int mat = blockIdx.x;
    const float* W; int koff;
    if (mat == 0)      { W = W1;  koff = 0;   }
    else if (mat == 1) { W = W1;  koff = 128; }
    else if (mat == 2) { W = W2;  koff = 0;   }
    else               { W = Wa1; koff = 0;   }
    __half* dh = (__half*)(g_wsw + (size_t)mat * 65536);
    __half* dl = dh + 16384;
    for (int idx = threadIdx.x; idx < 16384; idx += blockDim.x) {
        int n = idx >> 7, k = idx & 127;
        float w = W[(size_t)(koff + k) * 128 + n];   // B[n][k] = W[k][n]
        __half h = __float2half_rn(w);
        __half l = __float2half_rn(w - __half2float(h));
        dh[n * 128 + k] = h;
        dl[n * 128 + k] = l;
    }
}

// ---------------- staging ----------------
__device__ __forceinline__ void stage_w_async(uint32_t smb, int mat, int tid) {
    const unsigned char* src = g_wsw + (size_t)mat * 65536;
    unsigned long long gbase = (unsigned long long)__cvta_generic_to_global((void*)src);
#pragma unroll
    for (int i = 0; i < 8; i++) {
        int idx = tid + i * 256;
        int r = idx >> 4, q = idx & 15;
        uint32_t soff = (uint32_t)(r * 136 + q * 8) * 2u;
        unsigned long long goff = (unsigned long long)(r * 128 + q * 8) * 2ull;
        CP_ASYNC16(smb + B_HI_OFF + soff,       gbase + goff);
        CP_ASYNC16(smb + B_HI_OFF + BLO + soff, gbase + 32768ull + goff);
    }
}

// ---------------- inner: 8 n16-tiles of B, 2-pass (B hi + B lo) ----------------
__device__ __forceinline__ void mma_inner(uint32_t smb, uint32_t bRow, uint32_t bK0, int ks,
                                          const uint32_t* a, float (*acc)[4]) {
#pragma unroll
    for (int nt2 = 0; nt2 < 8; nt2++) {
        uint32_t bh[4], bl[4];
        uint32_t baddr = smb + B_HI_OFF +
            (bRow + (uint32_t)nt2 * (16u * 136u) + bK0 + (uint32_t)ks * 16u) * 2u;
        LDM4(bh, baddr);
        LDM4(bl, baddr + BLO);
        MMA16816(acc[2 * nt2],     a, bh[0], bh[1]);
        MMA16816(acc[2 * nt2 + 1], a, bh[2], bh[3]);
        MMA16816(acc[2 * nt2],     a, bl[0], bl[1]);
        MMA16816(acc[2 * nt2 + 1], a, bl[2], bl[3]);
    }
}

// single-pass inner (B hi only) — used for the attention GEMM
__device__ __forceinline__ void mma_inner_hi(uint32_t smb, uint32_t bRow, uint32_t bK0, int ks,
                                             const uint32_t* a, float (*acc)[4]) {
#pragma unroll
    for (int nt2 = 0; nt2 < 8; nt2++) {
        uint32_t bh[4];
        uint32_t baddr = smb + B_HI_OFF +
            (bRow + (uint32_t)nt2 * (16u * 136u) + bK0 + (uint32_t)ks * 16u) * 2u;
        LDM4(bh, baddr);
        MMA16816(acc[2 * nt2],     a, bh[0], bh[1]);
        MMA16816(acc[2 * nt2 + 1], a, bh[2], bh[3]);
    }
}

// phase-1 block: A straight from gmem x, software-pipelined (prefetch ks+1)
__device__ __forceinline__ void mma_block_g(uint32_t smb, const float* __restrict__ x,
                                            size_t rowTile, int hh, int w, int L,
                                            float (*acc)[4]) {
    const int g = L >> 2, t = L & 3;
    const float* p0 = x + (rowTile + (size_t)(w * 16 + g)) * DIN + hh * 128 + 2 * t;
    const float* p1 = p0 + 8 * DIN;
    const int g3 = L >> 3, rr = L & 7;
    const uint32_t bRow = (uint32_t)((g3 >> 1) * 8 + rr) * 136u;
    const uint32_t bK0  = 8u * (uint32_t)(g3 & 1);

    float2 v0 = *(const float2*)(p0);
    float2 v1 = *(const float2*)(p1);
    float2 v2 = *(const float2*)(p0 + 8);
    float2 v3 = *(const float2*)(p1 + 8);
#pragma unroll
    for (int ks = 0; ks < 8; ks++) {
        float2 n0, n1, n2, n3;
        if (ks < 7) {
            n0 = *(const float2*)(p0 + (ks + 1) * 16);
            n1 = *(const float2*)(p1 + (ks + 1) * 16);
            n2 = *(const float2*)(p0 + (ks + 1) * 16 + 8);
            n3 = *(const float2*)(p1 + (ks + 1) * 16 + 8);
        }
        uint32_t a[4];
        a[0] = pack_h2(v0.x, v0.y);
        a[1] = pack_h2(v1.x, v1.y);
        a[2] = pack_h2(v2.x, v2.y);
        a[3] = pack_h2(v3.x, v3.y);
        mma_inner(smb, bRow, bK0, ks, a, acc);
        if (ks < 7) { v0 = n0; v1 = n1; v2 = n2; v3 = n3; }
    }
}

// phase-2 block: A entirely from regs (afh), 2-pass B
__device__ __forceinline__ void mma_block_r(uint32_t smb, const uint32_t* afh, int L,
                                            float (*acc)[4]) {
    const int g3 = L >> 3, rr = L & 7;
    const uint32_t bRow = (uint32_t)((g3 >> 1) * 8 + rr) * 136u;
    const uint32_t bK0  = 8u * (uint32_t)(g3 & 1);
#pragma unroll 2
    for (int ks = 0; ks < 8; ks++)
        mma_inner(smb, bRow, bK0, ks, afh + ks * 4, acc);
}

// phase-3 block: A from regs, single-pass B (hi only)
__device__ __forceinline__ void mma_block_r1(uint32_t smb, const uint32_t* afh, int L,
                                             float (*acc)[4]) {
    const int g3 = L >> 3, rr = L & 7;
    const uint32_t bRow = (uint32_t)((g3 >> 1) * 8 + rr) * 136u;
    const uint32_t bK0  = 8u * (uint32_t)(g3 & 1);
#pragma unroll 2
    for (int ks = 0; ks < 8; ks++)
        mma_inner_hi(smb, bRow, bK0, ks, afh + ks * 4, acc);
}

// repack C fragments (post-activation) into next-phase A fragments (fp16, regs only)
__device__ __forceinline__ void repack_A(float (*acc)[4], uint32_t* afh) {
#pragma unroll
    for (int j = 0; j < 8; j++) {
        afh[4 * j]     = pack_h2(acc[2 * j][0],     acc[2 * j][1]);
        afh[4 * j + 1] = pack_h2(acc[2 * j][2],     acc[2 * j][3]);
        afh[4 * j + 2] = pack_h2(acc[2 * j + 1][0], acc[2 * j + 1][1]);
        afh[4 * j + 3] = pack_h2(acc[2 * j + 1][2], acc[2 * j + 1][3]);
    }
}

// ---------------- LN + ReLU epilogue (full row per warp, shuffle-only) ----------------
__device__ __forceinline__ void ln_relu(float (*acc)[4], const float* bias, int boff, int L) {
    const int q2 = 2 * (L & 3);
    float s0 = 0.f, s1 = 0.f;
#pragma unroll
    for (int nt = 0; nt < 16; nt++) {
        int c = nt * 8 + q2;
        float b0 = bias[boff + c], b1v = bias[boff + c + 1];
        acc[nt][0] += b0; acc[nt][1] += b1v; acc[nt][2] += b0; acc[nt][3] += b1v;
        s0 += acc[nt][0] + acc[nt][1];
        s1 += acc[nt][2] + acc[nt][3];
    }
    s0 += __shfl_xor_sync(0xffffffffu, s0, 1); s0 += __shfl_xor_sync(0xffffffffu, s0, 2);
    s1 += __shfl_xor_sync(0xffffffffu, s1, 1); s1 += __shfl_xor_sync(0xffffffffu, s1, 2);
    float mu0 = s0 * 0.0078125f, mu1 = s1 * 0.0078125f;
    float v0 = 0.f, v1 = 0.f;
#pragma unroll
    for (int nt = 0; nt < 16; nt++) {
        float d;
        d = acc[nt][0] - mu0; v0 = fmaf(d, d, v0);
        d = acc[nt][1] - mu0; v0 = fmaf(d, d, v0);
        d = acc[nt][2] - mu1; v1 = fmaf(d, d, v1);
        d = acc[nt][3] - mu1; v1 = fmaf(d, d, v1);
    }
    v0 += __shfl_xor_sync(0xffffffffu, v0, 1); v0 += __shfl_xor_sync(0xffffffffu, v0, 2);
    v1 += __shfl_xor_sync(0xffffffffu, v1, 1); v1 += __shfl_xor_sync(0xffffffffu, v1, 2);
    float i0 = rsqrtf(fmaf(v0, 0.0078125f, LN_EPS));
    float i1 = rsqrtf(fmaf(v1, 0.0078125f, LN_EPS));
#pragma unroll
    for (int nt = 0; nt < 16; nt++) {
        int c = nt * 8 + q2;
        float g0 = bias[boff + 128 + c], g1v = bias[boff + 128 + c + 1];
        float e0 = bias[boff + 256 + c], e1v = bias[boff + 256 + c + 1];
        acc[nt][0] = fmaxf(fmaf((acc[nt][0] - mu0) * i0, g0, e0), 0.f);
        acc[nt][1] = fmaxf(fmaf((acc[nt][1] - mu0) * i0, g1v, e1v), 0.f);
        acc[nt][2] = fmaxf(fmaf((acc[nt][2] - mu1) * i1, g0, e0), 0.f);
        acc[nt][3] = fmaxf(fmaf((acc[nt][3] - mu1) * i1, g1v, e1v), 0.f);
    }
}

// ---------------- fused row kernel (2 CTAs/SM) ----------------
__global__ void __launch_bounds__(256, 2)
k_rows_mma(const float* __restrict__ x,
           const float* __restrict__ b1, const float* __restrict__ g1, const float* __restrict__ be1,
           const float* __restrict__ b2, const float* __restrict__ g2, const float* __restrict__ be2,
           const float* __restrict__ ba1, const float* __restrict__ ba2, const float* __restrict__ Wa2)
{
    extern __shared__ char sm[];
    const uint32_t smb = smem_to_u32(sm);
    const int tid = threadIdx.x;
    const int w = tid >> 5, L = tid & 31;
    const size_t rowTile = (size_t)blockIdx.x * 128;
    float* bias = (float*)(sm + BIAS_OFF);

    stage_w_async(smb, 0, tid); CP_COMMIT();   // W1 half0

    if (tid < 128) {
        bias[tid]       = b1[tid];  bias[128 + tid] = g1[tid];  bias[256 + tid] = be1[tid];
        bias[384 + tid] = b2[tid];  bias[512 + tid] = g2[tid];  bias[640 + tid] = be2[tid];
        bias[768 + tid] = ba1[tid]; bias[896 + tid] = Wa2[tid];
    }
    if (tid == 0) bias[1024] = ba2[0];

    float acc[16][4];
#pragma unroll
    for (int nt = 0; nt < 16; nt++)
#pragma unroll
        for (int j = 0; j < 4; j++) acc[nt][j] = 0.f;

    // ===== PHASE 1: x @ W1 (K=256, two K=128 blocks; A from gmem, pipelined) =====
    CP_WAIT(0);
    __syncthreads();
    mma_block_g(smb, x, rowTile, 0, w, L, acc);
    __syncthreads();
    stage_w_async(smb, 1, tid); CP_COMMIT();   // W1 half1
    CP_WAIT(0);
    __syncthreads();
    mma_block_g(smb, x, rowTile, 1, w, L, acc);
    __syncthreads();
    stage_w_async(smb, 2, tid); CP_COMMIT();   // W2 (overlaps LN1 epilogue)

    uint32_t afh[32];
    ln_relu(acc, bias, 0, L);
    repack_A(acc, afh);                        // h1 -> A frags (regs only)
    CP_WAIT(0);
    __syncthreads();

    // ===== PHASE 2: h1 @ W2 =====
#pragma unroll
    for (int nt = 0; nt < 16; nt++)
#pragma unroll
        for (int j = 0; j < 4; j++) acc[nt][j] = 0.f;
    mma_block_r(smb, afh, L, acc);
    __syncthreads();
    stage_w_async(smb, 3, tid); CP_COMMIT();   // Wa1 (overlaps LN2 epilogue + h2 store)

    ln_relu(acc, bias, 384, L);
    // h2 -> gmem bf16, direct from fragments (all 32B sectors fully covered)
    {
        const int r0 = w * 16 + (L >> 2), r1 = r0 + 8;
        const int q2 = 2 * (L & 3);
        __nv_bfloat16* h0p = g_h2b + (rowTile + r0) * HDIM;
        __nv_bfloat16* h1p = g_h2b + (rowTile + r1) * HDIM;
#pragma unroll
        for (int nt = 0; nt < 16; nt++) {
            int c = nt * 8 + q2;
            *(uint32_t*)(h0p + c) = pack_bf(acc[nt][0], acc[nt][1]);
            *(uint32_t*)(h1p + c) = pack_bf(acc[nt][2], acc[nt][3]);
        }
    }
    repack_A(acc, afh);                        // h2 -> A frags
    CP_WAIT(0);
    __syncthreads();

    // ===== PHASE 3: h2 @ Wa1 (hi-only) -> tanh -> dot Wa2 -> scores =====
#pragma unroll
    for (int nt = 0; nt < 16; nt++)
#pragma unroll
        for (int j = 0; j < 4; j++) acc[nt][j] = 0.f;
    mma_block_r1(smb, afh, L, acc);

    {
        const int r0 = w * 16 + (L >> 2), r1 = r0 + 8;
        const int q2 = 2 * (L & 3);
        float p0 = 0.f, p1 = 0.f;
#pragma unroll
        for (int nt = 0; nt < 16; nt++) {
            int c = nt * 8 + q2;
            float wa0 = bias[896 + c], wa1v = bias[896 + c + 1];
            float bb0 = bias[768 + c], bb1 = bias[768 + c + 1];
            p0 = fmaf(fast_tanh(acc[nt][0] + bb0), wa0, p0);
            p0 = fmaf(fast_tanh(acc[nt][1] + bb1), wa1v, p0);
            p1 = fmaf(fast_tanh(acc[nt][2] + bb0), wa0, p1);
            p1 = fmaf(fast_tanh(acc[nt][3] + bb1), wa1v, p1);
        }
        p0 += __shfl_xor_sync(0xffffffffu, p0, 1); p0 += __shfl_xor_sync(0xffffffffu, p0, 2);
        p1 += __shfl_xor_sync(0xffffffffu, p1, 1); p1 += __shfl_xor_sync(0xffffffffu, p1, 2);
        if ((L & 3) == 0) {
            float bb = bias[1024];
            g_scores[rowTile + r0] = p0 + bb;
            g_scores[rowTile + r1] = p1 + bb;
        }
    }
}

// ---------------- per-bag score max (1024 thr, float4) ----------------
__global__ __launch_bounds__(1024)
void k_max()
{
    const int bag = blockIdx.x;
    const int tid = threadIdx.x;
    __shared__ float red[1024];
    float m = -3.4e38f;
    const float4* sp = (const float4*)(g_scores + (size_t)bag * NPER);
    for (int i = tid; i < NPER / 4; i += 1024) {
        float4 v = sp[i];
        m = fmaxf(m, fmaxf(fmaxf(v.x, v.y), fmaxf(v.z, v.w)));
    }
    red[tid] = m;
    __syncthreads();
    for (int off = 512; off; off >>= 1) {
        if (tid < off) red[tid] = fmaxf(red[tid], red[tid + off]);
        __syncthreads();
    }
    if (tid == 0) g_bagmax[bag] = red[0];
}

// ---------------- weighted partial sums (chunks of 512 rows, bf16 h2, MLP 8) ----------------
__global__ __launch_bounds__(256)
void k_wsum()
{
    const int b = blockIdx.x / NCHUNK2;
    const int c = blockIdx.x % NCHUNK2;
    const int tid = threadIdx.x;
    const int base = c * CHUNK;
    const int cnt = min(CHUNK, NPER - base);
    __shared__ float wrow[CHUNK];
    __shared__ float2 sred[256];

    const float bm = g_bagmax[b];
    {
        int i0 = tid, i1 = tid + 256;
        wrow[i0] = (i0 < cnt) ? expf((g_scores[(size_t)b * NPER + base + i0] - bm) * INV_TAU) : 0.f;
        wrow[i1] = (i1 < cnt) ? expf((g_scores[(size_t)b * NPER + base + i1] - bm) * INV_TAU) : 0.f;
    }
    __syncthreads();

    const int c2 = tid & 63;
    const int rg = tid >> 6;
    const uint32_t* hp = (const uint32_t*)(g_h2b + ((size_t)b * NPER + base) * HDIM) + c2;

    float2 a0 = {0.f,0.f}, a1 = {0.f,0.f}, a2 = {0.f,0.f}, a3 = {0.f,0.f};
    int n = rg;
    for (; n + 28 < cnt; n += 32) {
        uint32_t u[8];
#pragma unroll
        for (int j = 0; j < 8; j++) u[j] = hp[(size_t)(n + 4 * j) * 64];
#pragma unroll
        for (int j = 0; j < 8; j += 4) {
            float2 f0 = __bfloat1622float2(*(const __nv_bfloat162*)&u[j]);
            float2 f1 = __bfloat1622float2(*(const __nv_bfloat162*)&u[j + 1]);
            float2 f2 = __bfloat1622float2(*(const __nv_bfloat162*)&u[j + 2]);
            float2 f3 = __bfloat1622float2(*(const __nv_bfloat162*)&u[j + 3]);
            float w0 = wrow[n + 4 * j], w1 = wrow[n + 4 * j + 4];
            float w2 = wrow[n + 4 * j + 8], w3 = wrow[n + 4 * j + 12];
            a0.x = fmaf(w0, f0.x, a0.x); a0.y = fmaf(w0, f0.y, a0.y);
            a1.x = fmaf(w1, f1.x, a1.x); a1.y = fmaf(w1, f1.y, a1.y);
            a2.x = fmaf(w2, f2.x, a2.x); a2.y = fmaf(w2, f2.y, a2.y);
            a3.x = fmaf(w3, f3.x, a3.x); a3.y = fmaf(w3, f3.y, a3.y);
        }
    }
    for (; n < cnt; n += 4) {
        uint32_t u = hp[(size_t)n * 64];
        float2 f = __bfloat1622float2(*(const __nv_bfloat162*)&u);
        float wv = wrow[n];
        a0.x = fmaf(wv, f.x, a0.x); a0.y = fmaf(wv, f.y, a0.y);
    }
    float2 at;
    at.x = (a0.x + a1.x) + (a2.x + a3.x);
    at.y = (a0.y + a1.y) + (a2.y + a3.y);
    sred[tid] = at;
    __syncthreads();
    if (tid < 64) {
        float2 t0 = sred[tid], t1 = sred[tid + 64], t2 = sred[tid + 128], t3 = sred[tid + 192];
        float* pv = g_pvec + ((size_t)b * NCHUNK2 + c) * HDIM;
        pv[2 * tid]     = (t0.x + t1.x) + (t2.x + t3.x);
        pv[2 * tid + 1] = (t0.y + t1.y) + (t2.y + t3.y);
    }

    __syncthreads();
    float z = wrow[tid] + wrow[tid + 256];
    wrow[tid] = z;
    __syncthreads();
    for (int off = 128; off; off >>= 1) {
        if (tid < off) wrow[tid] += wrow[tid + off];
        __syncthreads();
    }
    if (tid == 0) g_pZ[b * NCHUNK2 + c] = wrow[0];
}

// ---------------- final heads ----------------
__global__ __launch_bounds__(128)
void k_final(const float* __restrict__ Wc1, const float* __restrict__ bc1,
             const float* __restrict__ Wc2, const float* __restrict__ bc2,
             const float* __restrict__ Ws1, const float* __restrict__ bs1,
             const float* __restrict__ Ws2, const float* __restrict__ bs2,
             float* __restrict__ out)
{
    const int bag = blockIdx.x;
    const int tid = threadIdx.x;
    __shared__ float bagn[128];
    __shared__ float hid[128];
    __shared__ float redz[128];
    __shared__ float hs[64];

    float vv = 0.0f;
    for (int c = 0; c < NCHUNK2; c++)
        vv += g_pvec[((size_t)bag * NCHUNK2 + c) * HDIM + tid];

    float zp = 0.0f;
    for (int c = tid; c < NCHUNK2; c += 128)
        zp += g_pZ[bag * NCHUNK2 + c];
    redz[tid] = zp;
    __syncthreads();
    for (int off = 64; off; off >>= 1) {
        if (tid < off) redz[tid] += redz[tid + off];
        __syncthreads();
    }
    const float Z = redz[0];
    bagn[tid] = vv / Z;
    __syncthreads();

    {
        float h = bc1[tid];
        for (int k = 0; k < 128; k++) h = fmaf(bagn[k], Wc1[k * 128 + tid], h);
        hid[tid] = fmaxf(h, 0.0f);
    }
    if (tid < 64) {
        float h = bs1[tid];
        for (int k = 0; k < 128; k++) h = fmaf(bagn[k], Ws1[k * 64 + tid], h);
        hs[tid] = fmaxf(h, 0.0f);
    }
    __syncthreads();

    if (tid < 2) {
        float s = bc2[tid];
        for (int j = 0; j < 128; j++) s = fmaf(hid[j], Wc2[j * 2 + tid], s);
        out[bag * 2 + tid] = s;
    }
    if (tid == 2) {
        float r = bs2[0];
        for (int j = 0; j < 64; j++) r = fmaf(hs[j], Ws2[j], r);
        out[16 + bag] = r;
    }
}

extern "C" void kernel_launch(void* const* d_in, const int* in_sizes, int n_in,
                              void* d_out, int out_size)
{
    const float* x   = (const float*)d_in[0];
    const float* W1  = (const float*)d_in[1];
    const float* b1  = (const float*)d_in[2];
    const float* g1  = (const float*)d_in[3];
    const float* be1 = (const float*)d_in[4];
    const float* W2  = (const float*)d_in[5];
    const float* b2  = (const float*)d_in[6];
    const float* g2  = (const float*)d_in[7];
    const float* be2 = (const float*)d_in[8];
    const float* Wa1 = (const float*)d_in[9];
    const float* ba1 = (const float*)d_in[10];
    const float* Wa2 = (const float*)d_in[11];
    const float* ba2 = (const float*)d_in[12];
    const float* Wc1 = (const float*)d_in[13];
    const float* bc1 = (const float*)d_in[14];
    const float* Wc2 = (const float*)d_in[15];
    const float* bc2 = (const float*)d_in[16];
    const float* Ws1 = (const float*)d_in[17];
    const float* bs1 = (const float*)d_in[18];
    const float* Ws2 = (const float*)d_in[19];
    const float* bs2 = (const float*)d_in[20];
    float* out = (float*)d_out;

    cudaFuncSetAttribute(k_rows_mma, cudaFuncAttributeMaxDynamicSharedMemorySize, SMEM_SZ);

    k_prep<<<4, 256>>>(W1, W2, Wa1);
    k_rows_mma<<<MROWS / 128, 256, SMEM_SZ>>>(x, b1, g1, be1, b2, g2, be2, ba1, ba2, Wa2);
    k_max<<<NBAG, 1024>>>();
    k_wsum<<<NBAG * NCHUNK2, 256>>>();
    k_final<<<NBAG, 128>>>(Wc1, bc1, Wc2, bc2, Ws1, bs1, Ws2, bs2, out);
}

// round 11
// speedup vs baseline: 1.8195x; 1.1481x over previous
#include <cuda_runtime.h>
#include <cuda_bf16.h>
#include <cuda_fp16.h>
#include <math.h>
#include <stdint.h>

// ---------------- problem constants ----------------
#define MROWS   400000
#define NBAG    8
#define NPER    50000
#define DIN     256
#define HDIM    128
#define INV_TAU (1.0f/0.3f)
#define LN_EPS  1e-5f
#define CHUNK   512
#define NCHUNK2 98               // ceil(50000/512)

// ---------------- scratch globals ----------------
__device__ __nv_bfloat16 g_h2b[(size_t)MROWS * HDIM];   // 102.4 MB (bf16)
__device__ float g_scores[MROWS];
__device__ float g_bagmax[NBAG];
__device__ float g_pvec[NBAG * NCHUNK2 * HDIM];
__device__ float g_pZ[NBAG * NCHUNK2];
// fp16 hi/lo weights, dense [n][k]: [W1half0, W1half1, W2, Wa1] x [hi 32KB | lo 32KB]
__device__ __align__(16) unsigned char g_wsw[4 * 65536];

// ---------------- smem layout (bytes), single CTA = 73744 -> 2 CTAs/SM ----------------
#define B_HI_OFF  0              // weight buffer hi [128][136] fp16
#define BLO       34816          // hi -> lo offset
#define BIAS_OFF  69632          // 1025 floats
#define SMEM_SZ   73744

__device__ __forceinline__ uint32_t smem_to_u32(const void* p) {
    uint32_t a;
    asm("{ .reg .u64 t; cvta.to.shared.u64 t, %1; cvt.u32.u64 %0, t; }" : "=r"(a) : "l"(p));
    return a;
}

#define LDM4(r, addr) \
    asm volatile("ldmatrix.sync.aligned.m8n8.x4.shared.b16 {%0,%1,%2,%3}, [%4];" \
        : "=r"((r)[0]), "=r"((r)[1]), "=r"((r)[2]), "=r"((r)[3]) : "r"(addr))

#define MMA16816(c, a, b0, b1) \
    asm volatile("mma.sync.aligned.m16n8k16.row.col.f32.f16.f16.f32 " \
        "{%0,%1,%2,%3}, {%4,%5,%6,%7}, {%8,%9}, {%0,%1,%2,%3};" \
        : "+f"((c)[0]), "+f"((c)[1]), "+f"((c)[2]), "+f"((c)[3]) \
        : "r"((a)[0]), "r"((a)[1]), "r"((a)[2]), "r"((a)[3]), "r"(b0), "r"(b1))

// .ca: cache staged weights in L1 so the sibling CTA on the same SM hits L1
#define CP_ASYNC16(saddr, gptr) \
    asm volatile("cp.async.ca.shared.global [%0], [%1], 16;" :: "r"(saddr), "l"(gptr) : "memory")
#define CP_COMMIT() asm volatile("cp.async.commit_group;" ::: "memory")
#define CP_WAIT(n)  asm volatile("cp.async.wait_group %0;" :: "n"(n) : "memory")

// exact identity tanh: 1 - 2/(e^{2x}+1); abs err ~1e-7
__device__ __forceinline__ float fast_tanh(float x) {
    float e = __expf(2.0f * x);
    return 1.0f - __fdividef(2.0f, e + 1.0f);
}

__device__ __forceinline__ uint32_t pack_h2(float a, float b) {
    __half2 h = __floats2half2_rn(a, b);
    return *(uint32_t*)&h;
}
__device__ __forceinline__ uint32_t pack_bf(float a, float b) {
    return (uint32_t)__bfloat16_as_ushort(__float2bfloat16(a)) |
           ((uint32_t)__bfloat16_as_ushort(__float2bfloat16(b)) << 16);
}

// ---------------- weight prep: fp32 -> dense fp16 hi/lo [n][k] ----------------
__global__ void k_prep(const float* __restrict__ W1, const float* __restrict__ W2,
                       const float* __restrict__ Wa1)
{
    int mat = blockIdx.x;
    const float* W; int koff;
    if (mat == 0)      { W = W1;  koff = 0;   }
    else if (mat == 1) { W = W1;  koff = 128; }
    else if (mat == 2) { W = W2;  koff = 0;   }
    else               { W = Wa1; koff = 0;   }
    __half* dh = (__half*)(g_wsw + (size_t)mat * 65536);
    __half* dl = dh + 16384;
    for (int idx = threadIdx.x; idx < 16384; idx += blockDim.x) {
        int n = idx >> 7, k = idx & 127;
        float w = W[(size_t)(koff + k) * 128 + n];   // B[n][k] = W[k][n]
        __half h = __float2half_rn(w);
        __half l = __float2half_rn(w - __half2float(h));
        dh[n * 128 + k] = h;
        dl[n * 128 + k] = l;
    }
}

// ---------------- staging ----------------
// full stage (hi + lo) — used for W2 (2-pass phase)
__device__ __forceinline__ void stage_w_async(uint32_t smb, int mat, int tid) {
    const unsigned char* src = g_wsw + (size_t)mat * 65536;
    unsigned long long gbase = (unsigned long long)__cvta_generic_to_global((void*)src);
#pragma unroll
    for (int i = 0; i < 8; i++) {
        int idx = tid + i * 256;
        int r = idx >> 4, q = idx & 15;
        uint32_t soff = (uint32_t)(r * 136 + q * 8) * 2u;
        unsigned long long goff = (unsigned long long)(r * 128 + q * 8) * 2ull;
        CP_ASYNC16(smb + B_HI_OFF + soff,       gbase + goff);
        CP_ASYNC16(smb + B_HI_OFF + BLO + soff, gbase + 32768ull + goff);
    }
}
// hi-only stage — used for W1 halves + Wa1 (single-pass phases)
__device__ __forceinline__ void stage_w_async_hi(uint32_t smb, int mat, int tid) {
    const unsigned char* src = g_wsw + (size_t)mat * 65536;
    unsigned long long gbase = (unsigned long long)__cvta_generic_to_global((void*)src);
#pragma unroll
    for (int i = 0; i < 8; i++) {
        int idx = tid + i * 256;
        int r = idx >> 4, q = idx & 15;
        uint32_t soff = (uint32_t)(r * 136 + q * 8) * 2u;
        unsigned long long goff = (unsigned long long)(r * 128 + q * 8) * 2ull;
        CP_ASYNC16(smb + B_HI_OFF + soff, gbase + goff);
    }
}

// ---------------- inners with explicit B prefetch ----------------
// 2-pass (B hi + B lo)
__device__ __forceinline__ void mma_inner(uint32_t smb, uint32_t bRow, uint32_t bK0, int ks,
                                          const uint32_t* a, float (*acc)[4]) {
    uint32_t base = smb + B_HI_OFF + (bRow + bK0 + (uint32_t)ks * 16u) * 2u;
    uint32_t bh[4], bl[4];
    LDM4(bh, base);
    LDM4(bl, base + BLO);
#pragma unroll
    for (int nt2 = 0; nt2 < 8; nt2++) {
        uint32_t nh[4], nl[4];
        if (nt2 < 7) {
            uint32_t naddr = base + (uint32_t)(nt2 + 1) * (16u * 136u * 2u);
            LDM4(nh, naddr);
            LDM4(nl, naddr + BLO);
        }
        MMA16816(acc[2 * nt2],     a, bh[0], bh[1]);
        MMA16816(acc[2 * nt2 + 1], a, bh[2], bh[3]);
        MMA16816(acc[2 * nt2],     a, bl[0], bl[1]);
        MMA16816(acc[2 * nt2 + 1], a, bl[2], bl[3]);
        if (nt2 < 7) {
#pragma unroll
            for (int j = 0; j < 4; j++) { bh[j] = nh[j]; bl[j] = nl[j]; }
        }
    }
}

// single-pass (B hi only)
__device__ __forceinline__ void mma_inner_hi(uint32_t smb, uint32_t bRow, uint32_t bK0, int ks,
                                             const uint32_t* a, float (*acc)[4]) {
    uint32_t base = smb + B_HI_OFF + (bRow + bK0 + (uint32_t)ks * 16u) * 2u;
    uint32_t bh[4];
    LDM4(bh, base);
#pragma unroll
    for (int nt2 = 0; nt2 < 8; nt2++) {
        uint32_t nh[4];
        if (nt2 < 7) {
            LDM4(nh, base + (uint32_t)(nt2 + 1) * (16u * 136u * 2u));
        }
        MMA16816(acc[2 * nt2],     a, bh[0], bh[1]);
        MMA16816(acc[2 * nt2 + 1], a, bh[2], bh[3]);
        if (nt2 < 7) {
#pragma unroll
            for (int j = 0; j < 4; j++) bh[j] = nh[j];
        }
    }
}

// phase-1 block: A straight from gmem x, software-pipelined; B hi-only
__device__ __forceinline__ void mma_block_g(uint32_t smb, const float* __restrict__ x,
                                            size_t rowTile, int hh, int w, int L,
                                            float (*acc)[4]) {
    const int g = L >> 2, t = L & 3;
    const float* p0 = x + (rowTile + (size_t)(w * 16 + g)) * DIN + hh * 128 + 2 * t;
    const float* p1 = p0 + 8 * DIN;
    const int g3 = L >> 3, rr = L & 7;
    const uint32_t bRow = (uint32_t)((g3 >> 1) * 8 + rr) * 136u;
    const uint32_t bK0  = 8u * (uint32_t)(g3 & 1);

    float2 v0 = *(const float2*)(p0);
    float2 v1 = *(const float2*)(p1);
    float2 v2 = *(const float2*)(p0 + 8);
    float2 v3 = *(const float2*)(p1 + 8);
#pragma unroll
    for (int ks = 0; ks < 8; ks++) {
        float2 n0, n1, n2, n3;
        if (ks < 7) {
            n0 = *(const float2*)(p0 + (ks + 1) * 16);
            n1 = *(const float2*)(p1 + (ks + 1) * 16);
            n2 = *(const float2*)(p0 + (ks + 1) * 16 + 8);
            n3 = *(const float2*)(p1 + (ks + 1) * 16 + 8);
        }
        uint32_t a[4];
        a[0] = pack_h2(v0.x, v0.y);
        a[1] = pack_h2(v1.x, v1.y);
        a[2] = pack_h2(v2.x, v2.y);
        a[3] = pack_h2(v3.x, v3.y);
        mma_inner_hi(smb, bRow, bK0, ks, a, acc);
        if (ks < 7) { v0 = n0; v1 = n1; v2 = n2; v3 = n3; }
    }
}

// phase-2 block: A from regs (afh), 2-pass B
__device__ __forceinline__ void mma_block_r(uint32_t smb, const uint32_t* afh, int L,
                                            float (*acc)[4]) {
    const int g3 = L >> 3, rr = L & 7;
    const uint32_t bRow = (uint32_t)((g3 >> 1) * 8 + rr) * 136u;
    const uint32_t bK0  = 8u * (uint32_t)(g3 & 1);
#pragma unroll 2
    for (int ks = 0; ks < 8; ks++)
        mma_inner(smb, bRow, bK0, ks, afh + ks * 4, acc);
}

// phase-3 block: A from regs, single-pass B
__device__ __forceinline__ void mma_block_r1(uint32_t smb, const uint32_t* afh, int L,
                                             float (*acc)[4]) {
    const int g3 = L >> 3, rr = L & 7;
    const uint32_t bRow = (uint32_t)((g3 >> 1) * 8 + rr) * 136u;
    const uint32_t bK0  = 8u * (uint32_t)(g3 & 1);
#pragma unroll 2
    for (int ks = 0; ks < 8; ks++)
        mma_inner_hi(smb, bRow, bK0, ks, afh + ks * 4, acc);
}

// repack C fragments (post-activation) into next-phase A fragments (fp16, regs only)
__device__ __forceinline__ void repack_A(float (*acc)[4], uint32_t* afh) {
#pragma unroll
    for (int j = 0; j < 8; j++) {
        afh[4 * j]     = pack_h2(acc[2 * j][0],     acc[2 * j][1]);
        afh[4 * j + 1] = pack_h2(acc[2 * j][2],     acc[2 * j][3]);
        afh[4 * j + 2] = pack_h2(acc[2 * j + 1][0], acc[2 * j + 1][1]);
        afh[4 * j + 3] = pack_h2(acc[2 * j + 1][2], acc[2 * j + 1][3]);
    }
}

// ---------------- LN + ReLU epilogue (full row per warp, shuffle-only) ----------------
__device__ __forceinline__ void ln_relu(float (*acc)[4], const float* bias, int boff, int L) {
    const int q2 = 2 * (L & 3);
    float s0 = 0.f, s1 = 0.f;
#pragma unroll
    for (int nt = 0; nt < 16; nt++) {
        int c = nt * 8 + q2;
        float b0 = bias[boff + c], b1v = bias[boff + c + 1];
        acc[nt][0] += b0; acc[nt][1] += b1v; acc[nt][2] += b0; acc[nt][3] += b1v;
        s0 += acc[nt][0] + acc[nt][1];
        s1 += acc[nt][2] + acc[nt][3];
    }
    s0 += __shfl_xor_sync(0xffffffffu, s0, 1); s0 += __shfl_xor_sync(0xffffffffu, s0, 2);
    s1 += __shfl_xor_sync(0xffffffffu, s1, 1); s1 += __shfl_xor_sync(0xffffffffu, s1, 2);
    float mu0 = s0 * 0.0078125f, mu1 = s1 * 0.0078125f;
    float v0 = 0.f, v1 = 0.f;
#pragma unroll
    for (int nt = 0; nt < 16; nt++) {
        float d;
        d = acc[nt][0] - mu0; v0 = fmaf(d, d, v0);
        d = acc[nt][1] - mu0; v0 = fmaf(d, d, v0);
        d = acc[nt][2] - mu1; v1 = fmaf(d, d, v1);
        d = acc[nt][3] - mu1; v1 = fmaf(d, d, v1);
    }
    v0 += __shfl_xor_sync(0xffffffffu, v0, 1); v0 += __shfl_xor_sync(0xffffffffu, v0, 2);
    v1 += __shfl_xor_sync(0xffffffffu, v1, 1); v1 += __shfl_xor_sync(0xffffffffu, v1, 2);
    float i0 = rsqrtf(fmaf(v0, 0.0078125f, LN_EPS));
    float i1 = rsqrtf(fmaf(v1, 0.0078125f, LN_EPS));
#pragma unroll
    for (int nt = 0; nt < 16; nt++) {
        int c = nt * 8 + q2;
        float g0 = bias[boff + 128 + c], g1v = bias[boff + 128 + c + 1];
        float e0 = bias[boff + 256 + c], e1v = bias[boff + 256 + c + 1];
        acc[nt][0] = fmaxf(fmaf((acc[nt][0] - mu0) * i0, g0, e0), 0.f);
        acc[nt][1] = fmaxf(fmaf((acc[nt][1] - mu0) * i0, g1v, e1v), 0.f);
        acc[nt][2] = fmaxf(fmaf((acc[nt][2] - mu1) * i1, g0, e0), 0.f);
        acc[nt][3] = fmaxf(fmaf((acc[nt][3] - mu1) * i1, g1v, e1v), 0.f);
    }
}

// ---------------- fused row kernel (2 CTAs/SM) ----------------
__global__ void __launch_bounds__(256, 2)
k_rows_mma(const float* __restrict__ x,
           const float* __restrict__ b1, const float* __restrict__ g1, const float* __restrict__ be1,
           const float* __restrict__ b2, const float* __restrict__ g2, const float* __restrict__ be2,
           const float* __restrict__ ba1, const float* __restrict__ ba2, const float* __restrict__ Wa2)
{
    extern __shared__ char sm[];
    const uint32_t smb = smem_to_u32(sm);
    const int tid = threadIdx.x;
    const int w = tid >> 5, L = tid & 31;
    const size_t rowTile = (size_t)blockIdx.x * 128;
    float* bias = (float*)(sm + BIAS_OFF);

    stage_w_async_hi(smb, 0, tid); CP_COMMIT();   // W1 half0 (hi only)

    if (tid < 128) {
        bias[tid]       = b1[tid];  bias[128 + tid] = g1[tid];  bias[256 + tid] = be1[tid];
        bias[384 + tid] = b2[tid];  bias[512 + tid] = g2[tid];  bias[640 + tid] = be2[tid];
        bias[768 + tid] = ba1[tid]; bias[896 + tid] = Wa2[tid];
    }
    if (tid == 0) bias[1024] = ba2[0];

    float acc[16][4];
#pragma unroll
    for (int nt = 0; nt < 16; nt++)
#pragma unroll
        for (int j = 0; j < 4; j++) acc[nt][j] = 0.f;

    // ===== PHASE 1: x @ W1 (K=256, two K=128 blocks; A from gmem; hi-only B) =====
    CP_WAIT(0);
    __syncthreads();
    mma_block_g(smb, x, rowTile, 0, w, L, acc);
    __syncthreads();
    stage_w_async_hi(smb, 1, tid); CP_COMMIT();   // W1 half1 (hi only)
    CP_WAIT(0);
    __syncthreads();
    mma_block_g(smb, x, rowTile, 1, w, L, acc);
    __syncthreads();
    stage_w_async(smb, 2, tid); CP_COMMIT();      // W2 hi+lo (overlaps LN1 epilogue)

    uint32_t afh[32];
    ln_relu(acc, bias, 0, L);
    repack_A(acc, afh);                           // h1 -> A frags (regs only)
    CP_WAIT(0);
    __syncthreads();

    // ===== PHASE 2: h1 @ W2 (2-pass) =====
#pragma unroll
    for (int nt = 0; nt < 16; nt++)
#pragma unroll
        for (int j = 0; j < 4; j++) acc[nt][j] = 0.f;
    mma_block_r(smb, afh, L, acc);
    __syncthreads();
    stage_w_async_hi(smb, 3, tid); CP_COMMIT();   // Wa1 hi (overlaps LN2 + h2 store)

    ln_relu(acc, bias, 384, L);
    // h2 -> gmem bf16, direct from fragments (all 32B sectors fully covered)
    {
        const int r0 = w * 16 + (L >> 2), r1 = r0 + 8;
        const int q2 = 2 * (L & 3);
        __nv_bfloat16* h0p = g_h2b + (rowTile + r0) * HDIM;
        __nv_bfloat16* h1p = g_h2b + (rowTile + r1) * HDIM;
#pragma unroll
        for (int nt = 0; nt < 16; nt++) {
            int c = nt * 8 + q2;
            *(uint32_t*)(h0p + c) = pack_bf(acc[nt][0], acc[nt][1]);
            *(uint32_t*)(h1p + c) = pack_bf(acc[nt][2], acc[nt][3]);
        }
    }
    repack_A(acc, afh);                           // h2 -> A frags
    CP_WAIT(0);
    __syncthreads();

    // ===== PHASE 3: h2 @ Wa1 (hi-only) -> tanh -> dot Wa2 -> scores =====
#pragma unroll
    for (int nt = 0; nt < 16; nt++)
#pragma unroll
        for (int j = 0; j < 4; j++) acc[nt][j] = 0.f;
    mma_block_r1(smb, afh, L, acc);

    {
        const int r0 = w * 16 + (L >> 2), r1 = r0 + 8;
        const int q2 = 2 * (L & 3);
        float p0 = 0.f, p1 = 0.f;
#pragma unroll
        for (int nt = 0; nt < 16; nt++) {
            int c = nt * 8 + q2;
            float wa0 = bias[896 + c], wa1v = bias[896 + c + 1];
            float bb0 = bias[768 + c], bb1 = bias[768 + c + 1];
            p0 = fmaf(fast_tanh(acc[nt][0] + bb0), wa0, p0);
            p0 = fmaf(fast_tanh(acc[nt][1] + bb1), wa1v, p0);
            p1 = fmaf(fast_tanh(acc[nt][2] + bb0), wa0, p1);
            p1 = fmaf(fast_tanh(acc[nt][3] + bb1), wa1v, p1);
        }
        p0 += __shfl_xor_sync(0xffffffffu, p0, 1); p0 += __shfl_xor_sync(0xffffffffu, p0, 2);
        p1 += __shfl_xor_sync(0xffffffffu, p1, 1); p1 += __shfl_xor_sync(0xffffffffu, p1, 2);
        if ((L & 3) == 0) {
            float bb = bias[1024];
            g_scores[rowTile + r0] = p0 + bb;
            g_scores[rowTile + r1] = p1 + bb;
        }
    }
}

// ---------------- per-bag score max (1024 thr, float4) ----------------
__global__ __launch_bounds__(1024)
void k_max()
{
    const int bag = blockIdx.x;
    const int tid = threadIdx.x;
    __shared__ float red[1024];
    float m = -3.4e38f;
    const float4* sp = (const float4*)(g_scores + (size_t)bag * NPER);
    for (int i = tid; i < NPER / 4; i += 1024) {
        float4 v = sp[i];
        m = fmaxf(m, fmaxf(fmaxf(v.x, v.y), fmaxf(v.z, v.w)));
    }
    red[tid] = m;
    __syncthreads();
    for (int off = 512; off; off >>= 1) {
        if (tid < off) red[tid] = fmaxf(red[tid], red[tid + off]);
        __syncthreads();
    }
    if (tid == 0) g_bagmax[bag] = red[0];
}

// ---------------- weighted partial sums (chunks of 512 rows, bf16 h2, MLP 8) ----------------
__global__ __launch_bounds__(256)
void k_wsum()
{
    const int b = blockIdx.x / NCHUNK2;
    const int c = blockIdx.x % NCHUNK2;
    const int tid = threadIdx.x;
    const int base = c * CHUNK;
    const int cnt = min(CHUNK, NPER - base);
    __shared__ float wrow[CHUNK];
    __shared__ float2 sred[256];

    const float bm = g_bagmax[b];
    {
        int i0 = tid, i1 = tid + 256;
        wrow[i0] = (i0 < cnt) ? expf((g_scores[(size_t)b * NPER + base + i0] - bm) * INV_TAU) : 0.f;
        wrow[i1] = (i1 < cnt) ? expf((g_scores[(size_t)b * NPER + base + i1] - bm) * INV_TAU) : 0.f;
    }
    __syncthreads();

    const int c2 = tid & 63;
    const int rg = tid >> 6;
    const uint32_t* hp = (const uint32_t*)(g_h2b + ((size_t)b * NPER + base) * HDIM) + c2;

    float2 a0 = {0.f,0.f}, a1 = {0.f,0.f}, a2 = {0.f,0.f}, a3 = {0.f,0.f};
    int n = rg;
    for (; n + 28 < cnt; n += 32) {
        uint32_t u[8];
#pragma unroll
        for (int j = 0; j < 8; j++) u[j] = hp[(size_t)(n + 4 * j) * 64];
#pragma unroll
        for (int j = 0; j < 8; j += 4) {
            float2 f0 = __bfloat1622float2(*(const __nv_bfloat162*)&u[j]);
            float2 f1 = __bfloat1622float2(*(const __nv_bfloat162*)&u[j + 1]);
            float2 f2 = __bfloat1622float2(*(const __nv_bfloat162*)&u[j + 2]);
            float2 f3 = __bfloat1622float2(*(const __nv_bfloat162*)&u[j + 3]);
            float w0 = wrow[n + 4 * j], w1 = wrow[n + 4 * j + 4];
            float w2 = wrow[n + 4 * j + 8], w3 = wrow[n + 4 * j + 12];
            a0.x = fmaf(w0, f0.x, a0.x); a0.y = fmaf(w0, f0.y, a0.y);
            a1.x = fmaf(w1, f1.x, a1.x); a1.y = fmaf(w1, f1.y, a1.y);
            a2.x = fmaf(w2, f2.x, a2.x); a2.y = fmaf(w2, f2.y, a2.y);
            a3.x = fmaf(w3, f3.x, a3.x); a3.y = fmaf(w3, f3.y, a3.y);
        }
    }
    for (; n < cnt; n += 4) {
        uint32_t u = hp[(size_t)n * 64];
        float2 f = __bfloat1622float2(*(const __nv_bfloat162*)&u);
        float wv = wrow[n];
        a0.x = fmaf(wv, f.x, a0.x); a0.y = fmaf(wv, f.y, a0.y);
    }
    float2 at;
    at.x = (a0.x + a1.x) + (a2.x + a3.x);
    at.y = (a0.y + a1.y) + (a2.y + a3.y);
    sred[tid] = at;
    __syncthreads();
    if (tid < 64) {
        float2 t0 = sred[tid], t1 = sred[tid + 64], t2 = sred[tid + 128], t3 = sred[tid + 192];
        float* pv = g_pvec + ((size_t)b * NCHUNK2 + c) * HDIM;
        pv[2 * tid]     = (t0.x + t1.x) + (t2.x + t3.x);
        pv[2 * tid + 1] = (t0.y + t1.y) + (t2.y + t3.y);
    }

    __syncthreads();
    float z = wrow[tid] + wrow[tid + 256];
    wrow[tid] = z;
    __syncthreads();
    for (int off = 128; off; off >>= 1) {
        if (tid < off) wrow[tid] += wrow[tid + off];
        __syncthreads();
    }
    if (tid == 0) g_pZ[b * NCHUNK2 + c] = wrow[0];
}

// ---------------- final heads ----------------
__global__ __launch_bounds__(128)
void k_final(const float* __restrict__ Wc1, const float* __restrict__ bc1,
             const float* __restrict__ Wc2, const float* __restrict__ bc2,
             const float* __restrict__ Ws1, const float* __restrict__ bs1,
             const float* __restrict__ Ws2, const float* __restrict__ bs2,
             float* __restrict__ out)
{
    const int bag = blockIdx.x;
    const int tid = threadIdx.x;
    __shared__ float bagn[128];
    __shared__ float hid[128];
    __shared__ float redz[128];
    __shared__ float hs[64];

    float vv = 0.0f;
    for (int c = 0; c < NCHUNK2; c++)
        vv += g_pvec[((size_t)bag * NCHUNK2 + c) * HDIM + tid];

    float zp = 0.0f;
    for (int c = tid; c < NCHUNK2; c += 128)
        zp += g_pZ[bag * NCHUNK2 + c];
    redz[tid] = zp;
    __syncthreads();
    for (int off = 64; off; off >>= 1) {
        if (tid < off) redz[tid] += redz[tid + off];
        __syncthreads();
    }
    const float Z = redz[0];
    bagn[tid] = vv / Z;
    __syncthreads();

    {
        float h = bc1[tid];
        for (int k = 0; k < 128; k++) h = fmaf(bagn[k], Wc1[k * 128 + tid], h);
        hid[tid] = fmaxf(h, 0.0f);
    }
    if (tid < 64) {
        float h = bs1[tid];
        for (int k = 0; k < 128; k++) h = fmaf(bagn[k], Ws1[k * 64 + tid], h);
        hs[tid] = fmaxf(h, 0.0f);
    }
    __syncthreads();

    if (tid < 2) {
        float s = bc2[tid];
        for (int j = 0; j < 128; j++) s = fmaf(hid[j], Wc2[j * 2 + tid], s);
        out[bag * 2 + tid] = s;
    }
    if (tid == 2) {
        float r = bs2[0];
        for (int j = 0; j < 64; j++) r = fmaf(hs[j], Ws2[j], r);
        out[16 + bag] = r;
    }
}

extern "C" void kernel_launch(void* const* d_in, const int* in_sizes, int n_in,
                              void* d_out, int out_size)
{
    const float* x   = (const float*)d_in[0];
    const float* W1  = (const float*)d_in[1];
    const float* b1  = (const float*)d_in[2];
    const float* g1  = (const float*)d_in[3];
    const float* be1 = (const float*)d_in[4];
    const float* W2  = (const float*)d_in[5];
    const float* b2  = (const float*)d_in[6];
    const float* g2  = (const float*)d_in[7];
    const float* be2 = (const float*)d_in[8];
    const float* Wa1 = (const float*)d_in[9];
    const float* ba1 = (const float*)d_in[10];
    const float* Wa2 = (const float*)d_in[11];
    const float* ba2 = (const float*)d_in[12];
    const float* Wc1 = (const float*)d_in[13];
    const float* bc1 = (const float*)d_in[14];
    const float* Wc2 = (const float*)d_in[15];
    const float* bc2 = (const float*)d_in[16];
    const float* Ws1 = (const float*)d_in[17];
    const float* bs1 = (const float*)d_in[18];
    const float* Ws2 = (const float*)d_in[19];
    const float* bs2 = (const float*)d_in[20];
    float* out = (float*)d_out;

    cudaFuncSetAttribute(k_rows_mma, cudaFuncAttributeMaxDynamicSharedMemorySize, SMEM_SZ);

    k_prep<<<4, 256>>>(W1, W2, Wa1);
    k_rows_mma<<<MROWS / 128, 256, SMEM_SZ>>>(x, b1, g1, be1, b2, g2, be2, ba1, ba2, Wa2);
    k_max<<<NBAG, 1024>>>();
    k_wsum<<<NBAG * NCHUNK2, 256>>>();
    k_final<<<NBAG, 128>>>(Wc1, bc1, Wc2, bc2, Ws1, bs1, Ws2, bs2, out);
}

// round 12
// speedup vs baseline: 1.9868x; 1.0920x over previous
#include <cuda_runtime.h>
#include <cuda_bf16.h>
#include <cuda_fp16.h>
#include <math.h>
#include <stdint.h>

// ---------------- problem constants ----------------
#define MROWS   400000
#define NBAG    8
#define NPER    50000
#define DIN     256
#define HDIM    128
#define INV_TAU (1.0f/0.3f)
#define LN_EPS  1e-5f
#define CHUNK   512
#define NCHUNK2 98               // ceil(50000/512)

// ---------------- scratch globals ----------------
__device__ __nv_bfloat16 g_h2b[(size_t)MROWS * HDIM];   // 102.4 MB (bf16)
__device__ float g_scores[MROWS];
__device__ float g_bagmax[NBAG];
__device__ float g_pvec[NBAG * NCHUNK2 * HDIM];
__device__ float g_pZ[NBAG * NCHUNK2];
// fp16 weights (hi of round-to-nearest), dense [n][k]: [W1half0, W1half1, W2, Wa1]
__device__ __align__(16) unsigned char g_wsw[4 * 32768];

// ---------------- smem layout (bytes), single CTA = 38928 -> 2+ CTAs/SM ----------------
#define B_HI_OFF  0              // weight buffer [128][136] fp16 (34816 B)
#define BIAS_OFF  34816          // 1025 floats
#define SMEM_SZ   38928

__device__ __forceinline__ uint32_t smem_to_u32(const void* p) {
    uint32_t a;
    asm("{ .reg .u64 t; cvta.to.shared.u64 t, %1; cvt.u32.u64 %0, t; }" : "=r"(a) : "l"(p));
    return a;
}

#define LDM4(r, addr) \
    asm volatile("ldmatrix.sync.aligned.m8n8.x4.shared.b16 {%0,%1,%2,%3}, [%4];" \
        : "=r"((r)[0]), "=r"((r)[1]), "=r"((r)[2]), "=r"((r)[3]) : "r"(addr))

#define MMA16816(c, a, b0, b1) \
    asm volatile("mma.sync.aligned.m16n8k16.row.col.f32.f16.f16.f32 " \
        "{%0,%1,%2,%3}, {%4,%5,%6,%7}, {%8,%9}, {%0,%1,%2,%3};" \
        : "+f"((c)[0]), "+f"((c)[1]), "+f"((c)[2]), "+f"((c)[3]) \
        : "r"((a)[0]), "r"((a)[1]), "r"((a)[2]), "r"((a)[3]), "r"(b0), "r"(b1))

// .ca: cache staged weights in L1 so the sibling CTA on the same SM hits L1
#define CP_ASYNC16(saddr, gptr) \
    asm volatile("cp.async.ca.shared.global [%0], [%1], 16;" :: "r"(saddr), "l"(gptr) : "memory")
#define CP_COMMIT() asm volatile("cp.async.commit_group;" ::: "memory")
#define CP_WAIT(n)  asm volatile("cp.async.wait_group %0;" :: "n"(n) : "memory")

// exact identity tanh: 1 - 2/(e^{2x}+1); abs err ~1e-7
__device__ __forceinline__ float fast_tanh(float x) {
    float e = __expf(2.0f * x);
    return 1.0f - __fdividef(2.0f, e + 1.0f);
}

__device__ __forceinline__ uint32_t pack_h2(float a, float b) {
    __half2 h = __floats2half2_rn(a, b);
    return *(uint32_t*)&h;
}
__device__ __forceinline__ uint32_t pack_bf(float a, float b) {
    return (uint32_t)__bfloat16_as_ushort(__float2bfloat16(a)) |
           ((uint32_t)__bfloat16_as_ushort(__float2bfloat16(b)) << 16);
}

// ---------------- weight prep: fp32 -> dense fp16 [n][k] ----------------
__global__ void k_prep(const float* __restrict__ W1, const float* __restrict__ W2,
                       const float* __restrict__ Wa1)
{
    int mat = blockIdx.x;
    const float* W; int koff;
    if (mat == 0)      { W = W1;  koff = 0;   }
    else if (mat == 1) { W = W1;  koff = 128; }
    else if (mat == 2) { W = W2;  koff = 0;   }
    else               { W = Wa1; koff = 0;   }
    __half* dh = (__half*)(g_wsw + (size_t)mat * 32768);
    for (int idx = threadIdx.x; idx < 16384; idx += blockDim.x) {
        int n = idx >> 7, k = idx & 127;
        dh[n * 128 + k] = __float2half_rn(W[(size_t)(koff + k) * 128 + n]);  // B[n][k]=W[k][n]
    }
}

// ---------------- staging (fp16, single buffer) ----------------
__device__ __forceinline__ void stage_w_async(uint32_t smb, int mat, int tid) {
    const unsigned char* src = g_wsw + (size_t)mat * 32768;
    unsigned long long gbase = (unsigned long long)__cvta_generic_to_global((void*)src);
#pragma unroll
    for (int i = 0; i < 8; i++) {
        int idx = tid + i * 256;
        int r = idx >> 4, q = idx & 15;
        uint32_t soff = (uint32_t)(r * 136 + q * 8) * 2u;
        unsigned long long goff = (unsigned long long)(r * 128 + q * 8) * 2ull;
        CP_ASYNC16(smb + B_HI_OFF + soff, gbase + goff);
    }
}

// ---------------- inner: 8 n16-tiles of B, single pass, explicit prefetch ----------------
__device__ __forceinline__ void mma_inner(uint32_t smb, uint32_t bRow, uint32_t bK0, int ks,
                                          const uint32_t* a, float (*acc)[4]) {
    uint32_t base = smb + B_HI_OFF + (bRow + bK0 + (uint32_t)ks * 16u) * 2u;
    uint32_t bh[4];
    LDM4(bh, base);
#pragma unroll
    for (int nt2 = 0; nt2 < 8; nt2++) {
        uint32_t nh[4];
        if (nt2 < 7) {
            LDM4(nh, base + (uint32_t)(nt2 + 1) * (16u * 136u * 2u));
        }
        MMA16816(acc[2 * nt2],     a, bh[0], bh[1]);
        MMA16816(acc[2 * nt2 + 1], a, bh[2], bh[3]);
        if (nt2 < 7) {
#pragma unroll
            for (int j = 0; j < 4; j++) bh[j] = nh[j];
        }
    }
}

// phase-1 block: A straight from gmem x, software-pipelined
__device__ __forceinline__ void mma_block_g(uint32_t smb, const float* __restrict__ x,
                                            size_t rowTile, int hh, int w, int L,
                                            float (*acc)[4]) {
    const int g = L >> 2, t = L & 3;
    const float* p0 = x + (rowTile + (size_t)(w * 16 + g)) * DIN + hh * 128 + 2 * t;
    const float* p1 = p0 + 8 * DIN;
    const int g3 = L >> 3, rr = L & 7;
    const uint32_t bRow = (uint32_t)((g3 >> 1) * 8 + rr) * 136u;
    const uint32_t bK0  = 8u * (uint32_t)(g3 & 1);

    float2 v0 = *(const float2*)(p0);
    float2 v1 = *(const float2*)(p1);
    float2 v2 = *(const float2*)(p0 + 8);
    float2 v3 = *(const float2*)(p1 + 8);
#pragma unroll
    for (int ks = 0; ks < 8; ks++) {
        float2 n0, n1, n2, n3;
        if (ks < 7) {
            n0 = *(const float2*)(p0 + (ks + 1) * 16);
            n1 = *(const float2*)(p1 + (ks + 1) * 16);
            n2 = *(const float2*)(p0 + (ks + 1) * 16 + 8);
            n3 = *(const float2*)(p1 + (ks + 1) * 16 + 8);
        }
        uint32_t a[4];
        a[0] = pack_h2(v0.x, v0.y);
        a[1] = pack_h2(v1.x, v1.y);
        a[2] = pack_h2(v2.x, v2.y);
        a[3] = pack_h2(v3.x, v3.y);
        mma_inner(smb, bRow, bK0, ks, a, acc);
        if (ks < 7) { v0 = n0; v1 = n1; v2 = n2; v3 = n3; }
    }
}

// phase-2/3 block: A from regs (afh)
__device__ __forceinline__ void mma_block_r(uint32_t smb, const uint32_t* afh, int L,
                                            float (*acc)[4]) {
    const int g3 = L >> 3, rr = L & 7;
    const uint32_t bRow = (uint32_t)((g3 >> 1) * 8 + rr) * 136u;
    const uint32_t bK0  = 8u * (uint32_t)(g3 & 1);
#pragma unroll 2
    for (int ks = 0; ks < 8; ks++)
        mma_inner(smb, bRow, bK0, ks, afh + ks * 4, acc);
}

// repack C fragments (post-activation) into next-phase A fragments (fp16, regs only)
__device__ __forceinline__ void repack_A(float (*acc)[4], uint32_t* afh) {
#pragma unroll
    for (int j = 0; j < 8; j++) {
        afh[4 * j]     = pack_h2(acc[2 * j][0],     acc[2 * j][1]);
        afh[4 * j + 1] = pack_h2(acc[2 * j][2],     acc[2 * j][3]);
        afh[4 * j + 2] = pack_h2(acc[2 * j + 1][0], acc[2 * j + 1][1]);
        afh[4 * j + 3] = pack_h2(acc[2 * j + 1][2], acc[2 * j + 1][3]);
    }
}

// ---------------- LN + ReLU epilogue (full row per warp, shuffle-only) ----------------
__device__ __forceinline__ void ln_relu(float (*acc)[4], const float* bias, int boff, int L) {
    const int q2 = 2 * (L & 3);
    float s0 = 0.f, s1 = 0.f;
#pragma unroll
    for (int nt = 0; nt < 16; nt++) {
        int c = nt * 8 + q2;
        float b0 = bias[boff + c], b1v = bias[boff + c + 1];
        acc[nt][0] += b0; acc[nt][1] += b1v; acc[nt][2] += b0; acc[nt][3] += b1v;
        s0 += acc[nt][0] + acc[nt][1];
        s1 += acc[nt][2] + acc[nt][3];
    }
    s0 += __shfl_xor_sync(0xffffffffu, s0, 1); s0 += __shfl_xor_sync(0xffffffffu, s0, 2);
    s1 += __shfl_xor_sync(0xffffffffu, s1, 1); s1 += __shfl_xor_sync(0xffffffffu, s1, 2);
    float mu0 = s0 * 0.0078125f, mu1 = s1 * 0.0078125f;
    float v0 = 0.f, v1 = 0.f;
#pragma unroll
    for (int nt = 0; nt < 16; nt++) {
        float d;
        d = acc[nt][0] - mu0; v0 = fmaf(d, d, v0);
        d = acc[nt][1] - mu0; v0 = fmaf(d, d, v0);
        d = acc[nt][2] - mu1; v1 = fmaf(d, d, v1);
        d = acc[nt][3] - mu1; v1 = fmaf(d, d, v1);
    }
    v0 += __shfl_xor_sync(0xffffffffu, v0, 1); v0 += __shfl_xor_sync(0xffffffffu, v0, 2);
    v1 += __shfl_xor_sync(0xffffffffu, v1, 1); v1 += __shfl_xor_sync(0xffffffffu, v1, 2);
    float i0 = rsqrtf(fmaf(v0, 0.0078125f, LN_EPS));
    float i1 = rsqrtf(fmaf(v1, 0.0078125f, LN_EPS));
#pragma unroll
    for (int nt = 0; nt < 16; nt++) {
        int c = nt * 8 + q2;
        float g0 = bias[boff + 128 + c], g1v = bias[boff + 128 + c + 1];
        float e0 = bias[boff + 256 + c], e1v = bias[boff + 256 + c + 1];
        acc[nt][0] = fmaxf(fmaf((acc[nt][0] - mu0) * i0, g0, e0), 0.f);
        acc[nt][1] = fmaxf(fmaf((acc[nt][1] - mu0) * i0, g1v, e1v), 0.f);
        acc[nt][2] = fmaxf(fmaf((acc[nt][2] - mu1) * i1, g0, e0), 0.f);
        acc[nt][3] = fmaxf(fmaf((acc[nt][3] - mu1) * i1, g1v, e1v), 0.f);
    }
}

// ---------------- fused row kernel (2 CTAs/SM) ----------------
__global__ void __launch_bounds__(256, 2)
k_rows_mma(const float* __restrict__ x,
           const float* __restrict__ b1, const float* __restrict__ g1, const float* __restrict__ be1,
           const float* __restrict__ b2, const float* __restrict__ g2, const float* __restrict__ be2,
           const float* __restrict__ ba1, const float* __restrict__ ba2, const float* __restrict__ Wa2)
{
    extern __shared__ char sm[];
    const uint32_t smb = smem_to_u32(sm);
    const int tid = threadIdx.x;
    const int w = tid >> 5, L = tid & 31;
    const size_t rowTile = (size_t)blockIdx.x * 128;
    float* bias = (float*)(sm + BIAS_OFF);

    stage_w_async(smb, 0, tid); CP_COMMIT();   // W1 half0

    if (tid < 128) {
        bias[tid]       = b1[tid];  bias[128 + tid] = g1[tid];  bias[256 + tid] = be1[tid];
        bias[384 + tid] = b2[tid];  bias[512 + tid] = g2[tid];  bias[640 + tid] = be2[tid];
        bias[768 + tid] = ba1[tid]; bias[896 + tid] = Wa2[tid];
    }
    if (tid == 0) bias[1024] = ba2[0];

    float acc[16][4];
#pragma unroll
    for (int nt = 0; nt < 16; nt++)
#pragma unroll
        for (int j = 0; j < 4; j++) acc[nt][j] = 0.f;

    // ===== PHASE 1: x @ W1 (K=256, two K=128 blocks; A from gmem) =====
    CP_WAIT(0);
    __syncthreads();
    mma_block_g(smb, x, rowTile, 0, w, L, acc);
    __syncthreads();
    stage_w_async(smb, 1, tid); CP_COMMIT();   // W1 half1
    CP_WAIT(0);
    __syncthreads();
    mma_block_g(smb, x, rowTile, 1, w, L, acc);
    __syncthreads();
    stage_w_async(smb, 2, tid); CP_COMMIT();   // W2 (overlaps LN1 epilogue)

    uint32_t afh[32];
    ln_relu(acc, bias, 0, L);
    repack_A(acc, afh);                        // h1 -> A frags (regs only)
    CP_WAIT(0);
    __syncthreads();

    // ===== PHASE 2: h1 @ W2 =====
#pragma unroll
    for (int nt = 0; nt < 16; nt++)
#pragma unroll
        for (int j = 0; j < 4; j++) acc[nt][j] = 0.f;
    mma_block_r(smb, afh, L, acc);
    __syncthreads();
    stage_w_async(smb, 3, tid); CP_COMMIT();   // Wa1 (overlaps LN2 + h2 store)

    ln_relu(acc, bias, 384, L);
    // h2 -> gmem bf16, direct from fragments (all 32B sectors fully covered)
    {
        const int r0 = w * 16 + (L >> 2), r1 = r0 + 8;
        const int q2 = 2 * (L & 3);
        __nv_bfloat16* h0p = g_h2b + (rowTile + r0) * HDIM;
        __nv_bfloat16* h1p = g_h2b + (rowTile + r1) * HDIM;
#pragma unroll
        for (int nt = 0; nt < 16; nt++) {
            int c = nt * 8 + q2;
            *(uint32_t*)(h0p + c) = pack_bf(acc[nt][0], acc[nt][1]);
            *(uint32_t*)(h1p + c) = pack_bf(acc[nt][2], acc[nt][3]);
        }
    }
    repack_A(acc, afh);                        // h2 -> A frags
    CP_WAIT(0);
    __syncthreads();

    // ===== PHASE 3: h2 @ Wa1 -> tanh -> dot Wa2 -> scores =====
#pragma unroll
    for (int nt = 0; nt < 16; nt++)
#pragma unroll
        for (int j = 0; j < 4; j++) acc[nt][j] = 0.f;
    mma_block_r(smb, afh, L, acc);

    {
        const int r0 = w * 16 + (L >> 2), r1 = r0 + 8;
        const int q2 = 2 * (L & 3);
        float p0 = 0.f, p1 = 0.f;
#pragma unroll
        for (int nt = 0; nt < 16; nt++) {
            int c = nt * 8 + q2;
            float wa0 = bias[896 + c], wa1v = bias[896 + c + 1];
            float bb0 = bias[768 + c], bb1 = bias[768 + c + 1];
            p0 = fmaf(fast_tanh(acc[nt][0] + bb0), wa0, p0);
            p0 = fmaf(fast_tanh(acc[nt][1] + bb1), wa1v, p0);
            p1 = fmaf(fast_tanh(acc[nt][2] + bb0), wa0, p1);
            p1 = fmaf(fast_tanh(acc[nt][3] + bb1), wa1v, p1);
        }
        p0 += __shfl_xor_sync(0xffffffffu, p0, 1); p0 += __shfl_xor_sync(0xffffffffu, p0, 2);
        p1 += __shfl_xor_sync(0xffffffffu, p1, 1); p1 += __shfl_xor_sync(0xffffffffu, p1, 2);
        if ((L & 3) == 0) {
            float bb = bias[1024];
            g_scores[rowTile + r0] = p0 + bb;
            g_scores[rowTile + r1] = p1 + bb;
        }
    }
}

// ---------------- per-bag score max (1024 thr, float4) ----------------
__global__ __launch_bounds__(1024)
void k_max()
{
    const int bag = blockIdx.x;
    const int tid = threadIdx.x;
    __shared__ float red[1024];
    float m = -3.4e38f;
    const float4* sp = (const float4*)(g_scores + (size_t)bag * NPER);
    for (int i = tid; i < NPER / 4; i += 1024) {
        float4 v = sp[i];
        m = fmaxf(m, fmaxf(fmaxf(v.x, v.y), fmaxf(v.z, v.w)));
    }
    red[tid] = m;
    __syncthreads();
    for (int off = 512; off; off >>= 1) {
        if (tid < off) red[tid] = fmaxf(red[tid], red[tid + off]);
        __syncthreads();
    }
    if (tid == 0) g_bagmax[bag] = red[0];
}

// ---------------- weighted partial sums (chunks of 512 rows, bf16 h2, MLP 8) ----------------
__global__ __launch_bounds__(256)
void k_wsum()
{
    const int b = blockIdx.x / NCHUNK2;
    const int c = blockIdx.x % NCHUNK2;
    const int tid = threadIdx.x;
    const int base = c * CHUNK;
    const int cnt = min(CHUNK, NPER - base);
    __shared__ float wrow[CHUNK];
    __shared__ float2 sred[256];

    const float bm = g_bagmax[b];
    {
        int i0 = tid, i1 = tid + 256;
        wrow[i0] = (i0 < cnt) ? expf((g_scores[(size_t)b * NPER + base + i0] - bm) * INV_TAU) : 0.f;
        wrow[i1] = (i1 < cnt) ? expf((g_scores[(size_t)b * NPER + base + i1] - bm) * INV_TAU) : 0.f;
    }
    __syncthreads();

    const int c2 = tid & 63;
    const int rg = tid >> 6;
    const uint32_t* hp = (const uint32_t*)(g_h2b + ((size_t)b * NPER + base) * HDIM) + c2;

    float2 a0 = {0.f,0.f}, a1 = {0.f,0.f}, a2 = {0.f,0.f}, a3 = {0.f,0.f};
    int n = rg;
    for (; n + 28 < cnt; n += 32) {
        uint32_t u[8];
#pragma unroll
        for (int j = 0; j < 8; j++) u[j] = hp[(size_t)(n + 4 * j) * 64];
#pragma unroll
        for (int j = 0; j < 8; j += 4) {
            float2 f0 = __bfloat1622float2(*(const __nv_bfloat162*)&u[j]);
            float2 f1 = __bfloat1622float2(*(const __nv_bfloat162*)&u[j + 1]);
            float2 f2 = __bfloat1622float2(*(const __nv_bfloat162*)&u[j + 2]);
            float2 f3 = __bfloat1622float2(*(const __nv_bfloat162*)&u[j + 3]);
            float w0 = wrow[n + 4 * j], w1 = wrow[n + 4 * j + 4];
            float w2 = wrow[n + 4 * j + 8], w3 = wrow[n + 4 * j + 12];
            a0.x = fmaf(w0, f0.x, a0.x); a0.y = fmaf(w0, f0.y, a0.y);
            a1.x = fmaf(w1, f1.x, a1.x); a1.y = fmaf(w1, f1.y, a1.y);
            a2.x = fmaf(w2, f2.x, a2.x); a2.y = fmaf(w2, f2.y, a2.y);
            a3.x = fmaf(w3, f3.x, a3.x); a3.y = fmaf(w3, f3.y, a3.y);
        }
    }
    for (; n < cnt; n += 4) {
        uint32_t u = hp[(size_t)n * 64];
        float2 f = __bfloat1622float2(*(const __nv_bfloat162*)&u);
        float wv = wrow[n];
        a0.x = fmaf(wv, f.x, a0.x); a0.y = fmaf(wv, f.y, a0.y);
    }
    float2 at;
    at.x = (a0.x + a1.x) + (a2.x + a3.x);
    at.y = (a0.y + a1.y) + (a2.y + a3.y);
    sred[tid] = at;
    __syncthreads();
    if (tid < 64) {
        float2 t0 = sred[tid], t1 = sred[tid + 64], t2 = sred[tid + 128], t3 = sred[tid + 192];
        float* pv = g_pvec + ((size_t)b * NCHUNK2 + c) * HDIM;
        pv[2 * tid]     = (t0.x + t1.x) + (t2.x + t3.x);
        pv[2 * tid + 1] = (t0.y + t1.y) + (t2.y + t3.y);
    }

    __syncthreads();
    float z = wrow[tid] + wrow[tid + 256];
    wrow[tid] = z;
    __syncthreads();
    for (int off = 128; off; off >>= 1) {
        if (tid < off) wrow[tid] += wrow[tid + off];
        __syncthreads();
    }
    if (tid == 0) g_pZ[b * NCHUNK2 + c] = wrow[0];
}

// ---------------- final heads ----------------
__global__ __launch_bounds__(128)
void k_final(const float* __restrict__ Wc1, const float* __restrict__ bc1,
             const float* __restrict__ Wc2, const float* __restrict__ bc2,
             const float* __restrict__ Ws1, const float* __restrict__ bs1,
             const float* __restrict__ Ws2, const float* __restrict__ bs2,
             float* __restrict__ out)
{
    const int bag = blockIdx.x;
    const int tid = threadIdx.x;
    __shared__ float bagn[128];
    __shared__ float hid[128];
    __shared__ float redz[128];
    __shared__ float hs[64];

    float vv = 0.0f;
    for (int c = 0; c < NCHUNK2; c++)
        vv += g_pvec[((size_t)bag * NCHUNK2 + c) * HDIM + tid];

    float zp = 0.0f;
    for (int c = tid; c < NCHUNK2; c += 128)
        zp += g_pZ[bag * NCHUNK2 + c];
    redz[tid] = zp;
    __syncthreads();
    for (int off = 64; off; off >>= 1) {
        if (tid < off) redz[tid] += redz[tid + off];
        __syncthreads();
    }
    const float Z = redz[0];
    bagn[tid] = vv / Z;
    __syncthreads();

    {
        float h = bc1[tid];
        for (int k = 0; k < 128; k++) h = fmaf(bagn[k], Wc1[k * 128 + tid], h);
        hid[tid] = fmaxf(h, 0.0f);
    }
    if (tid < 64) {
        float h = bs1[tid];
        for (int k = 0; k < 128; k++) h = fmaf(bagn[k], Ws1[k * 64 + tid], h);
        hs[tid] = fmaxf(h, 0.0f);
    }
    __syncthreads();

    if (tid < 2) {
        float s = bc2[tid];
        for (int j = 0; j < 128; j++) s = fmaf(hid[j], Wc2[j * 2 + tid], s);
        out[bag * 2 + tid] = s;
    }
    if (tid == 2) {
        float r = bs2[0];
        for (int j = 0; j < 64; j++) r = fmaf(hs[j], Ws2[j], r);
        out[16 + bag] = r;
    }
}

extern "C" void kernel_launch(void* const* d_in, const int* in_sizes, int n_in,
                              void* d_out, int out_size)
{
    const float* x   = (const float*)d_in[0];
    const float* W1  = (const float*)d_in[1];
    const float* b1  = (const float*)d_in[2];
    const float* g1  = (const float*)d_in[3];
    const float* be1 = (const float*)d_in[4];
    const float* W2  = (const float*)d_in[5];
    const float* b2  = (const float*)d_in[6];
    const float* g2  = (const float*)d_in[7];
    const float* be2 = (const float*)d_in[8];
    const float* Wa1 = (const float*)d_in[9];
    const float* ba1 = (const float*)d_in[10];
    const float* Wa2 = (const float*)d_in[11];
    const float* ba2 = (const float*)d_in[12];
    const float* Wc1 = (const float*)d_in[13];
    const float* bc1 = (const float*)d_in[14];
    const float* Wc2 = (const float*)d_in[15];
    const float* bc2 = (const float*)d_in[16];
    const float* Ws1 = (const float*)d_in[17];
    const float* bs1 = (const float*)d_in[18];
    const float* Ws2 = (const float*)d_in[19];
    const float* bs2 = (const float*)d_in[20];
    float* out = (float*)d_out;

    cudaFuncSetAttribute(k_rows_mma, cudaFuncAttributeMaxDynamicSharedMemorySize, SMEM_SZ);

    k_prep<<<4, 256>>>(W1, W2, Wa1);
    k_rows_mma<<<MROWS / 128, 256, SMEM_SZ>>>(x, b1, g1, be1, b2, g2, be2, ba1, ba2, Wa2);
    k_max<<<NBAG, 1024>>>();
    k_wsum<<<NBAG * NCHUNK2, 256>>>();
    k_final<<<NBAG, 128>>>(Wc1, bc1, Wc2, bc2, Ws1, bs1, Ws2, bs2, out);
}